// round 13
// baseline (speedup 1.0000x reference)
#include <cuda_runtime.h>
#include <math.h>

#define NN   50000
#define EE   800000
#define IN_C 128
#define HID  256
#define EMBD 128
#define RR   4
#define NBLK ((NN + 255) / 256)

// ---------------- scratch (device globals; no allocation) ----------------
__device__ int      g_deg[NN];
__device__ float    g_invdeg[NN];
__device__ int      g_cnt4[NN * RR];
__device__ float    g_invcnt4[NN * RR];
__device__ int      g_rowstart[NN];
__device__ int      g_cursor[NN];
__device__ int      g_bsum[256];
__device__ int      g_boff[256];
__device__ int      g_es[EE];
__device__ int      g_etl[EE];
__device__ float    g_xr[(size_t)NN * IN_C];
__device__ float    g_agg1[(size_t)NN * IN_C];
__device__ float    g_x1[(size_t)NN * HID];
__device__ float    g_agg2[(size_t)NN * HID];
__device__ float    g_xsage[(size_t)NN * HID];
__device__ float    g_h[(size_t)NN * 2 * HID];
__device__ float    g_als[NN * 2];
__device__ float    g_ald[NN * 2];
__device__ float    g_xgat[(size_t)NN * HID];
__device__ float    g_xt[(size_t)RR * NN * EMBD];
__device__ float    g_xrgcn[(size_t)NN * EMBD];
__device__ float    g_fb2[EMBD];
__device__ float    g_bt1r[256 * 128];
__device__ float    g_bt1l[256 * 128];
__device__ float    g_bt2[256 * 512];
__device__ float    g_btg[512 * 256];
__device__ float    g_btrel[RR * 128 * 256];
__device__ float    g_btfus[128 * 640];

__device__ __forceinline__ float lrelu(float v) { return v > 0.f ? v : 0.2f * v; }

__device__ __forceinline__ unsigned f2tf32(float f) {
    unsigned r;
    asm("cvt.rna.tf32.f32 %0, %1;" : "=r"(r) : "f"(f));
    return r;
}
__device__ __forceinline__ float rtf(float f) { return __uint_as_float(f2tf32(f)); }

__device__ __forceinline__ void cp16(unsigned sm, const void* gm) {
    asm volatile("cp.async.cg.shared.global [%0], [%1], 16;" :: "r"(sm), "l"(gm));
}
__device__ __forceinline__ void cpcommit() {
    asm volatile("cp.async.commit_group;");
}
template <int N>
__device__ __forceinline__ void cpwait() {
    asm volatile("cp.async.wait_group %0;" :: "n"(N));
}

// ---------------- zero / counts / scan / fill ----------------
__global__ void k_zero_small() {
    int i = blockIdx.x * blockDim.x + threadIdx.x;
    if (i < NN) { g_deg[i] = 0; g_cursor[i] = 0; }
    if (i < NN * RR) g_cnt4[i] = 0;
}

__global__ void k_count(const int* __restrict__ dst, const int* __restrict__ et) {
    int i = blockIdx.x * blockDim.x + threadIdx.x;
    if (i >= EE) return;
    int d = dst[i];
    atomicAdd(&g_deg[d], 1);
    atomicAdd(&g_cnt4[d * RR + et[i]], 1);
}

__global__ void k_scan1() {
    __shared__ int sh[256];
    int b = blockIdx.x, t = threadIdx.x;
    int i = b * 256 + t;
    int v = (i < NN) ? g_deg[i] : 0;
    sh[t] = v; __syncthreads();
    for (int o = 1; o < 256; o <<= 1) {
        int add = (t >= o) ? sh[t - o] : 0;
        __syncthreads();
        sh[t] += add;
        __syncthreads();
    }
    if (i < NN) g_rowstart[i] = sh[t] - v;
    if (t == 255) g_bsum[b] = sh[255];
}

__global__ void k_scan2() {
    __shared__ int sh[256];
    int t = threadIdx.x;
    int v = (t < NBLK) ? g_bsum[t] : 0;
    sh[t] = v; __syncthreads();
    for (int o = 1; o < 256; o <<= 1) {
        int add = (t >= o) ? sh[t - o] : 0;
        __syncthreads();
        sh[t] += add;
        __syncthreads();
    }
    g_boff[t] = sh[t] - v;
}

__global__ void k_scan3_inv() {
    int i = blockIdx.x * blockDim.x + threadIdx.x;
    if (i >= NN) return;
    g_rowstart[i] += g_boff[i >> 8];
    g_invdeg[i] = 1.f / fmaxf((float)g_deg[i], 1.f);
#pragma unroll
    for (int r = 0; r < RR; r++)
        g_invcnt4[i * RR + r] = 1.f / fmaxf((float)g_cnt4[i * RR + r], 1.f);
}

__global__ void k_fill(const int* __restrict__ src, const int* __restrict__ dst,
                       const int* __restrict__ et) {
    int e = blockIdx.x * blockDim.x + threadIdx.x;
    if (e >= EE) return;
    int d = dst[e];
    int pos = atomicAdd(&g_cursor[d], 1);
    int slot = g_rowstart[d] + pos;
    g_es[slot] = src[e];
    g_etl[slot] = et[e];
}

// ---------------- weight transpose (+tf32 round) ----------------
__global__ void k_transB(const float* __restrict__ B, float* __restrict__ Bt,
                         int K, int N, int ldBt, int kOff) {
    int i = blockIdx.x * blockDim.x + threadIdx.x;
    if (i >= K * N) return;
    int k = i / N, n = i % N;
    Bt[(size_t)n * ldBt + kOff + k] = rtf(B[(size_t)k * N + n]);
}

struct TSeg { const float* B; float* Bt; int K; int N; int ldBt; int kOff; };
struct TSegs { TSeg s[10]; };

__global__ void k_transAll(TSegs P) {
    TSeg sg = P.s[blockIdx.y];
    int i = blockIdx.x * blockDim.x + threadIdx.x;
    if (i >= sg.K * sg.N) return;
    int k = i / sg.N, n = i % sg.N;
    sg.Bt[(size_t)n * sg.ldBt + sg.kOff + k] = rtf(sg.B[(size_t)k * sg.N + n]);
}

__global__ void k_round4(const float4* __restrict__ in, float4* __restrict__ out, int n4) {
    int i = blockIdx.x * blockDim.x + threadIdx.x;
    if (i >= n4) return;
    float4 v = in[i];
    v.x = rtf(v.x); v.y = rtf(v.y); v.z = rtf(v.z); v.w = rtf(v.w);
    out[i] = v;
}

// ---------------- SAGE mean-gather: 8 edge-groups x (D/4) float4 lanes ----------------
template <int D>
__global__ __launch_bounds__(D * 2) void k_sage_gather(const float* __restrict__ xin,
                                                       float* __restrict__ agg) {
    constexpr int L = D / 4;
    __shared__ float4 sred[8][L];
    int n = blockIdx.x;
    int tid = threadIdx.x;
    int grp = tid / L, lane = tid % L;
    int base = g_rowstart[n], deg = g_deg[n];
    const float4* xin4 = (const float4*)xin;
    float4 acc = make_float4(0.f, 0.f, 0.f, 0.f);
    for (int j = grp; j < deg; j += 8) {
        int s = g_es[base + j];
        float4 v = xin4[(size_t)s * L + lane];
        acc.x += v.x; acc.y += v.y; acc.z += v.z; acc.w += v.w;
    }
    sred[grp][lane] = acc;
    __syncthreads();
    if (grp == 0) {
        float4 o = sred[0][lane];
#pragma unroll
        for (int g = 1; g < 8; g++) {
            float4 v = sred[g][lane];
            o.x += v.x; o.y += v.y; o.z += v.z; o.w += v.w;
        }
        float w = g_invdeg[n];
        o.x = rtf(o.x * w); o.y = rtf(o.y * w);
        o.z = rtf(o.z * w); o.w = rtf(o.w * w);
        ((float4*)agg)[(size_t)n * L + lane] = o;
    }
}

// ---------------- TF32 GEMM: 128x128, 4-stage cp.async pipeline, 1 sync/tile (R8) ----------------
__global__ __launch_bounds__(256) void tgemm(
    const float* __restrict__ A0, int K0,
    const float* __restrict__ A1, int K1,
    const float* __restrict__ A2, int K2,
    const float* __restrict__ Bt,
    float* __restrict__ C, const float* __restrict__ bias,
    int M, int Nc, int accFlag, int reluFlag, int roundFlag,
    size_t zsB, size_t zsC) {
    extern __shared__ float sm[];
    float* smA = sm;               // 4 * 2560 floats
    float* smB = sm + 4 * 2560;
#define ASX(st, r, c) smA[(st) * 2560 + (r) * 20 + (c)]
#define BSX(st, r, c) smB[(st) * 2560 + (r) * 20 + (c)]
    const int tid = threadIdx.x;
    const int m0 = blockIdx.y * 128, n0 = blockIdx.x * 128;
    const int wid = tid >> 5, lane = tid & 31;
    const int wm = wid & 3, wn = wid >> 2;
    const int g = lane >> 2, tq = lane & 3;
    const int Ktot = K0 + K1 + K2;
    Bt += blockIdx.z * zsB;
    C  += blockIdx.z * zsC;
    const float* segA[3] = {A0, A1, A2};
    const int segK01 = K0 + K1;
    const int T = Ktot >> 4;

    float acc[2][8][4];
#pragma unroll
    for (int mt = 0; mt < 2; mt++)
#pragma unroll
        for (int nt = 0; nt < 8; nt++)
#pragma unroll
            for (int r = 0; r < 4; r++) acc[mt][nt][r] = 0.f;

    const int aRow = tid >> 1;
    const int aCol = (tid & 1) * 8;
    const bool aValid = (m0 + aRow) < M;
    const int aR = aValid ? (m0 + aRow) : 0;
    const float* BtRow = Bt + (size_t)(n0 + aRow) * Ktot + aCol;

    const int aLr = (lane & 7) + (((lane >> 3) & 1) << 3);
    const int aLc = ((lane >> 4) & 1) * 4;
    const int bLr = (lane & 7) + (((lane >> 4) & 1) << 3);
    const int bLc = ((lane >> 3) & 1) * 4;

    auto issue = [&](int tile, int buf) {
        int kpos = tile * 16;
        int s, kk;
        if (kpos < K0) { s = 0; kk = kpos; }
        else if (kpos < segK01) { s = 1; kk = kpos - K0; }
        else { s = 2; kk = kpos - segK01; }
        int Ks = (s == 0) ? K0 : (s == 1) ? K1 : K2;
        const float* Ag = segA[s] + (size_t)aR * Ks + kk + aCol;
        unsigned sa = (unsigned)__cvta_generic_to_shared(&ASX(buf, aRow, aCol));
        cp16(sa, Ag); cp16(sa + 16, Ag + 4);
        const float* Bg = BtRow + kpos;
        unsigned sb = (unsigned)__cvta_generic_to_shared(&BSX(buf, aRow, aCol));
        cp16(sb, Bg); cp16(sb + 16, Bg + 4);
    };

    for (int p = 0; p < 3 && p < T; p++) { issue(p, p); cpcommit(); }

    for (int t = 0; t < T; t++) {
        cpwait<2>();
        __syncthreads();
        if (t + 3 < T) issue(t + 3, (t + 3) & 3);
        cpcommit();
        const int pb = t & 3;
#pragma unroll
        for (int ks = 0; ks < 16; ks += 8) {
            unsigned af[2][4], bf[4][4];
#pragma unroll
            for (int mt = 0; mt < 2; mt++) {
                unsigned addr = (unsigned)__cvta_generic_to_shared(
                    &ASX(pb, wm * 32 + mt * 16 + aLr, ks + aLc));
                asm volatile("ldmatrix.sync.aligned.m8n8.x4.shared.b16 {%0,%1,%2,%3}, [%4];"
                    : "=r"(af[mt][0]), "=r"(af[mt][1]), "=r"(af[mt][2]), "=r"(af[mt][3])
                    : "r"(addr));
            }
#pragma unroll
            for (int np = 0; np < 4; np++) {
                unsigned addr = (unsigned)__cvta_generic_to_shared(
                    &BSX(pb, wn * 64 + np * 16 + bLr, ks + bLc));
                asm volatile("ldmatrix.sync.aligned.m8n8.x4.shared.b16 {%0,%1,%2,%3}, [%4];"
                    : "=r"(bf[np][0]), "=r"(bf[np][1]), "=r"(bf[np][2]), "=r"(bf[np][3])
                    : "r"(addr));
            }
#pragma unroll
            for (int mt = 0; mt < 2; mt++)
#pragma unroll
                for (int nt = 0; nt < 8; nt++) {
                    unsigned b0 = bf[nt >> 1][(nt & 1) * 2 + 0];
                    unsigned b1 = bf[nt >> 1][(nt & 1) * 2 + 1];
                    float* c = acc[mt][nt];
                    asm volatile(
                        "mma.sync.aligned.m16n8k8.row.col.f32.tf32.tf32.f32 "
                        "{%0,%1,%2,%3}, {%4,%5,%6,%7}, {%8,%9}, {%0,%1,%2,%3};"
                        : "+f"(c[0]), "+f"(c[1]), "+f"(c[2]), "+f"(c[3])
                        : "r"(af[mt][0]), "r"(af[mt][1]), "r"(af[mt][2]), "r"(af[mt][3]),
                          "r"(b0), "r"(b1));
                }
        }
    }

#pragma unroll
    for (int mt = 0; mt < 2; mt++) {
        int r0 = m0 + wm * 32 + mt * 16 + g;
#pragma unroll
        for (int half = 0; half < 2; half++) {
            int row = r0 + half * 8;
            if (row >= M) continue;
#pragma unroll
            for (int nt = 0; nt < 8; nt++) {
                int col = n0 + wn * 64 + nt * 8 + 2 * tq;
                float* p = C + (size_t)row * Nc + col;
                float2 cv;
                cv.x = acc[mt][nt][half * 2 + 0];
                cv.y = acc[mt][nt][half * 2 + 1];
                if (accFlag) { float2 o = *(const float2*)p; cv.x += o.x; cv.y += o.y; }
                if (bias != nullptr) { cv.x += bias[col]; cv.y += bias[col + 1]; }
                if (reluFlag) { cv.x = fmaxf(cv.x, 0.f); cv.y = fmaxf(cv.y, 0.f); }
                if (roundFlag) { cv.x = rtf(cv.x); cv.y = rtf(cv.y); }
                *(float2*)p = cv;
            }
        }
    }
#undef ASX
#undef BSX
}

// ---------------- GAT: per-node attention logits (float4) ----------------
__global__ __launch_bounds__(256) void k_al(const float* __restrict__ aS,
                                            const float* __restrict__ aD) {
    int gw = (int)(((size_t)blockIdx.x * blockDim.x + threadIdx.x) >> 5);
    int lane = threadIdx.x & 31;
    if (gw >= NN * 2) return;
    int n = gw >> 1, k = gw & 1;
    const float4* hp = (const float4*)(g_h + (size_t)n * 512 + k * 256);
    const float4* as4 = (const float4*)(aS + k * 256);
    const float4* ad4 = (const float4*)(aD + k * 256);
    float ss = 0.f, sd = 0.f;
#pragma unroll
    for (int it = 0; it < 2; it++) {
        int j = lane + it * 32;
        float4 h = hp[j], A = as4[j], D = ad4[j];
        ss += h.x * A.x + h.y * A.y + h.z * A.z + h.w * A.w;
        sd += h.x * D.x + h.y * D.y + h.z * D.z + h.w * D.w;
    }
#pragma unroll
    for (int o = 16; o; o >>= 1) {
        ss += __shfl_down_sync(0xffffffffu, ss, o);
        sd += __shfl_down_sync(0xffffffffu, sd, o);
    }
    if (lane == 0) { g_als[gw] = ss; g_ald[gw] = sd; }
}

// ---------------- GAT: online-softmax, thread owns float2 of features ----------------
__global__ __launch_bounds__(256) void k_gat(const float* __restrict__ bias) {
    __shared__ float sW0[256], sW1[256];
    __shared__ int   sS[256];
    __shared__ float wm0[8], wm1[8];
    __shared__ float2 stage[128];
    int n = blockIdx.x;
    int t = threadIdx.x;
    int lane = t & 31, warp = t >> 5;
    int base = g_rowstart[n], deg = g_deg[n];

    float ald0 = g_ald[2 * n], ald1 = g_ald[2 * n + 1];
    float m0 = lrelu(g_als[2 * n] + ald0);
    float m1 = lrelu(g_als[2 * n + 1] + ald1);
    float d0 = 1.f, d1 = 1.f;
    const float2* h2 = (const float2*)g_h;
    float2 a = h2[(size_t)n * 256 + t];
    bool head0 = (t < 128);

    for (int c0 = 0; c0 < deg; c0 += 256) {
        int cnt = min(256, deg - c0);
        float e0 = -1e30f, e1 = -1e30f;
        int sNode = 0;
        if (t < cnt) {
            sNode = g_es[base + c0 + t];
            e0 = lrelu(g_als[2 * sNode] + ald0);
            e1 = lrelu(g_als[2 * sNode + 1] + ald1);
        }
        float w0r = e0, w1r = e1;
#pragma unroll
        for (int o = 16; o; o >>= 1) {
            w0r = fmaxf(w0r, __shfl_xor_sync(0xffffffffu, w0r, o));
            w1r = fmaxf(w1r, __shfl_xor_sync(0xffffffffu, w1r, o));
        }
        if (lane == 0) { wm0[warp] = w0r; wm1[warp] = w1r; }
        __syncthreads();
        float cm0 = wm0[0], cm1 = wm1[0];
#pragma unroll
        for (int w = 1; w < 8; w++) { cm0 = fmaxf(cm0, wm0[w]); cm1 = fmaxf(cm1, wm1[w]); }

        float M0 = fmaxf(m0, cm0), M1 = fmaxf(m1, cm1);
        float sc0 = expf(m0 - M0), sc1 = expf(m1 - M1);
        float scMe = head0 ? sc0 : sc1;
        a.x *= scMe; a.y *= scMe;
        d0 *= sc0; d1 *= sc1; m0 = M0; m1 = M1;

        if (t < cnt) {
            sS[t] = sNode;
            sW0[t] = expf(e0 - m0);
            sW1[t] = expf(e1 - m1);
        }
        __syncthreads();
        for (int j = 0; j < cnt; j++) {
            float w0 = sW0[j], w1 = sW1[j];
            float w = head0 ? w0 : w1;
            float2 hv = h2[(size_t)sS[j] * 256 + t];
            a.x += w * hv.x; a.y += w * hv.y;
            d0 += w0; d1 += w1;
        }
        __syncthreads();
    }
    float i0 = 1.f / fmaxf(d0, 1e-16f), i1 = 1.f / fmaxf(d1, 1e-16f);
    if (!head0) stage[t - 128] = a;
    __syncthreads();
    if (head0) {
        float2 b1 = stage[t];
        float v0 = 0.5f * (a.x * i0 + b1.x * i1) + bias[2 * t];
        float v1 = 0.5f * (a.y * i0 + b1.y * i1) + bias[2 * t + 1];
        float2 o;
        o.x = rtf(fmaxf(v0, 0.f));
        o.y = rtf(fmaxf(v1, 0.f));
        ((float2*)g_xgat)[(size_t)n * 128 + t] = o;
    }
}

// ---------------- RGCN gather: 8 edge-groups x 32 float4 lanes ----------------
__global__ __launch_bounds__(256) void k_rgcn() {
    __shared__ float4 sred[8][32];
    int n = blockIdx.x;
    int t = threadIdx.x;
    int grp = t >> 5, lane = t & 31;
    int base = g_rowstart[n], deg = g_deg[n];
    float w0 = g_invcnt4[n * 4 + 0], w1 = g_invcnt4[n * 4 + 1];
    float w2 = g_invcnt4[n * 4 + 2], w3 = g_invcnt4[n * 4 + 3];
    const float4* xt4 = (const float4*)g_xt;
    float4 acc = make_float4(0.f, 0.f, 0.f, 0.f);
    for (int j = grp; j < deg; j += 8) {
        int s = g_es[base + j];
        int r = g_etl[base + j];
        float w = (r == 0) ? w0 : (r == 1) ? w1 : (r == 2) ? w2 : w3;
        float4 v = xt4[((size_t)r * NN + s) * 32 + lane];
        acc.x += w * v.x; acc.y += w * v.y; acc.z += w * v.z; acc.w += w * v.w;
    }
    sred[grp][lane] = acc;
    __syncthreads();
    if (grp == 0) {
        float4 o = sred[0][lane];
#pragma unroll
        for (int g = 1; g < 8; g++) {
            float4 v = sred[g][lane];
            o.x += v.x; o.y += v.y; o.z += v.z; o.w += v.w;
        }
        o.x = rtf(o.x); o.y = rtf(o.y); o.z = rtf(o.z); o.w = rtf(o.w);
        ((float4*)g_xrgcn)[(size_t)n * 32 + lane] = o;
    }
}

// ---------------- fold rgcn root into fusion weights ----------------
__global__ void k_compose(const float* __restrict__ fW, const float* __restrict__ fB,
                          const float* __restrict__ Wroot, const float* __restrict__ rgcB,
                          float* __restrict__ btfus) {
    int b = blockIdx.x, t = threadIdx.x;
    const float* F3 = fW + 512 * EMBD;
    if (b < HID) {
        float acc = fW[(256 + b) * EMBD + t];
        for (int h = 0; h < EMBD; h++)
            acc += Wroot[b * EMBD + h] * F3[h * EMBD + t];
        btfus[(size_t)t * 640 + 256 + b] = rtf(acc);
    } else {
        float acc = fB[t];
        for (int h = 0; h < EMBD; h++)
            acc += rgcB[h] * F3[h * EMBD + t];
        g_fb2[t] = acc;
    }
}

// ---------------- final L2 normalize ----------------
__global__ void k_norm(float* __restrict__ out) {
    int n = blockIdx.x;
    int t = threadIdx.x;
    float v = out[(size_t)n * EMBD + t];
    float s = v * v;
#pragma unroll
    for (int o = 16; o; o >>= 1) s += __shfl_down_sync(0xffffffffu, s, o);
    __shared__ float sh[4];
    if ((t & 31) == 0) sh[t >> 5] = s;
    __syncthreads();
    float tot = sh[0] + sh[1] + sh[2] + sh[3];
    float nrm = fmaxf(sqrtf(tot), 1e-12f);
    out[(size_t)n * EMBD + t] = v / nrm;
}

// ---------------- host ----------------
#define TG_SMEM (4 * 2 * 2560 * 4)

static void launch_seg(const float* A0, int K0, const float* A1, int K1,
                       const float* A2, int K2, const float* Bt,
                       float* C, const float* bias, int M, int Nc,
                       int acc, int relu, int rnd,
                       int gz = 1, size_t zsB = 0, size_t zsC = 0) {
    dim3 grid(Nc / 128, (M + 127) / 128, gz);
    tgemm<<<grid, 256, TG_SMEM>>>(A0, K0, A1, K1, A2, K2, Bt, C, bias, M, Nc,
                                  acc, relu, rnd, zsB, zsC);
}

extern "C" void kernel_launch(void* const* d_in, const int* in_sizes, int n_in,
                              void* d_out, int out_size) {
    const float* x    = (const float*)d_in[0];
    const int*   ei   = (const int*)d_in[1];
    const int*   et   = (const int*)d_in[2];
    const float* s1Wl = (const float*)d_in[3];
    const float* s1Wr = (const float*)d_in[4];
    const float* s1b  = (const float*)d_in[5];
    const float* s2Wl = (const float*)d_in[6];
    const float* s2Wr = (const float*)d_in[7];
    const float* s2b  = (const float*)d_in[8];
    const float* gatW = (const float*)d_in[9];
    const float* aSrc = (const float*)d_in[10];
    const float* aDst = (const float*)d_in[11];
    const float* gatB = (const float*)d_in[12];
    const float* Wrel = (const float*)d_in[13];
    const float* Wroot= (const float*)d_in[14];
    const float* rgcB = (const float*)d_in[15];
    const float* fW   = (const float*)d_in[16];
    const float* fB   = (const float*)d_in[17];
    float* out = (float*)d_out;

    const int* src = ei;
    const int* dst = ei + EE;

    cudaFuncSetAttribute(tgemm, cudaFuncAttributeMaxDynamicSharedMemorySize, TG_SMEM);

    float *p_xr, *p_agg1, *p_x1, *p_agg2, *p_xsage, *p_h, *p_xgat, *p_xt, *p_xrgcn, *p_fb2;
    float *p_bt1r, *p_bt1l, *p_bt2, *p_btg, *p_btrel, *p_btfus;
    cudaGetSymbolAddress((void**)&p_xr, g_xr);
    cudaGetSymbolAddress((void**)&p_agg1, g_agg1);
    cudaGetSymbolAddress((void**)&p_x1, g_x1);
    cudaGetSymbolAddress((void**)&p_agg2, g_agg2);
    cudaGetSymbolAddress((void**)&p_xsage, g_xsage);
    cudaGetSymbolAddress((void**)&p_h, g_h);
    cudaGetSymbolAddress((void**)&p_xgat, g_xgat);
    cudaGetSymbolAddress((void**)&p_xt, g_xt);
    cudaGetSymbolAddress((void**)&p_xrgcn, g_xrgcn);
    cudaGetSymbolAddress((void**)&p_fb2, g_fb2);
    cudaGetSymbolAddress((void**)&p_bt1r, g_bt1r);
    cudaGetSymbolAddress((void**)&p_bt1l, g_bt1l);
    cudaGetSymbolAddress((void**)&p_bt2, g_bt2);
    cudaGetSymbolAddress((void**)&p_btg, g_btg);
    cudaGetSymbolAddress((void**)&p_btrel, g_btrel);
    cudaGetSymbolAddress((void**)&p_btfus, g_btfus);

    // launches 1-4 (ncu profiles #4 -> a GEMM)
    k_zero_small<<<(NN * RR + 255) / 256, 256>>>();                             // 1
    k_transB<<<(128 * 256 + 255) / 256, 256>>>(s1Wr, p_bt1r, 128, 256, 128, 0); // 2
    k_round4<<<(NN * IN_C / 4 + 255) / 256, 256>>>((const float4*)x, (float4*)p_xr,
                                                   NN * IN_C / 4);              // 3
    launch_seg(p_xr, IN_C, 0, 0, 0, 0, p_bt1r, p_x1, nullptr,
               NN, HID, 0, 0, 0);                                               // 4

    // CSR build
    k_count<<<(EE + 255) / 256, 256>>>(dst, et);
    k_scan1<<<NBLK, 256>>>();
    k_scan2<<<1, 256>>>();
    k_scan3_inv<<<NBLK, 256>>>();
    k_fill<<<(EE + 255) / 256, 256>>>(src, dst, et);

    // remaining weight transposes in one launch
    TSegs ts;
    ts.s[0] = {s1Wl, p_bt1l, 128, 256, 128, 0};
    ts.s[1] = {s2Wl, p_bt2, 256, 256, 512, 0};
    ts.s[2] = {s2Wr, p_bt2, 256, 256, 512, 256};
    ts.s[3] = {gatW, p_btg, 256, 512, 256, 0};
    ts.s[4] = {Wrel + 0 * (size_t)HID * EMBD, p_btrel + 0 * (size_t)128 * 256, 256, 128, 256, 0};
    ts.s[5] = {Wrel + 1 * (size_t)HID * EMBD, p_btrel + 1 * (size_t)128 * 256, 256, 128, 256, 0};
    ts.s[6] = {Wrel + 2 * (size_t)HID * EMBD, p_btrel + 2 * (size_t)128 * 256, 256, 128, 256, 0};
    ts.s[7] = {Wrel + 3 * (size_t)HID * EMBD, p_btrel + 3 * (size_t)128 * 256, 256, 128, 256, 0};
    ts.s[8] = {fW, p_btfus, 256, 128, 640, 0};
    ts.s[9] = {fW + 512 * EMBD, p_btfus, 128, 128, 640, 512};
    k_transAll<<<dim3(512, 10), 256>>>(ts);
    k_compose<<<HID + 1, EMBD>>>(fW, fB, Wroot, rgcB, p_btfus);

    // ---- SAGE 1 ----
    k_sage_gather<IN_C><<<NN, IN_C * 2>>>(x, p_agg1);
    launch_seg(p_agg1, IN_C, 0, 0, 0, 0, p_bt1l, p_x1, s1b, NN, HID, 1, 1, 1);

    // ---- SAGE 2 ----
    k_sage_gather<HID><<<NN, HID * 2>>>(p_x1, p_agg2);
    launch_seg(p_agg2, HID, p_x1, HID, 0, 0, p_bt2, p_xsage, s2b, NN, HID, 0, 1, 1);

    // ---- GAT ----
    launch_seg(p_xsage, HID, 0, 0, 0, 0, p_btg, p_h, nullptr, NN, 2 * HID, 0, 0, 0);
    k_al<<<(NN * 2 * 32 + 255) / 256, 256>>>(aSrc, aDst);
    k_gat<<<NN, 256>>>(gatB);

    // ---- RGCN ----
    launch_seg(p_xgat, HID, 0, 0, 0, 0, p_btrel, p_xt, nullptr, NN, EMBD, 0, 0, 0,
               RR, (size_t)128 * 256, (size_t)NN * EMBD);
    k_rgcn<<<NN, 256>>>();

    // ---- Fusion + normalize ----
    launch_seg(p_xsage, HID, p_xgat, HID, p_xrgcn, EMBD, p_btfus,
               out, p_fb2, NN, EMBD, 0, 0, 0);
    k_norm<<<NN, 128>>>(out);
}

// round 14
// speedup vs baseline: 1.1838x; 1.1838x over previous
#include <cuda_runtime.h>
#include <math.h>

#define NN   50000
#define EE   800000
#define IN_C 128
#define HID  256
#define EMBD 128
#define RR   4
#define NBLK ((NN + 255) / 256)

// ---------------- scratch (device globals; no allocation) ----------------
__device__ int      g_deg[NN];
__device__ float    g_invdeg[NN];
__device__ int      g_cnt4[NN * RR];
__device__ float    g_invcnt4[NN * RR];
__device__ int      g_rowstart[NN];
__device__ int      g_cursor[NN];
__device__ int      g_bsum[256];
__device__ int      g_boff[256];
__device__ int      g_es[EE];
__device__ int      g_etl[EE];
__device__ float    g_xr[(size_t)NN * IN_C];
__device__ float    g_agg1[(size_t)NN * IN_C];
__device__ float    g_x1[(size_t)NN * HID];
__device__ float    g_agg2[(size_t)NN * HID];
__device__ float    g_xsage[(size_t)NN * HID];
__device__ float    g_h[(size_t)NN * 2 * HID];
__device__ float    g_als[NN * 2];
__device__ float    g_ald[NN * 2];
__device__ float    g_xgat[(size_t)NN * HID];
__device__ float    g_xt[(size_t)RR * NN * EMBD];
__device__ float    g_xrgcn[(size_t)NN * EMBD];
__device__ float    g_fb2[EMBD];
__device__ float    g_bt1[256 * 256];     // stacked: k 0..127 = s1Wl, 128..255 = s1Wr
__device__ float    g_bt2[256 * 512];
__device__ float    g_btg[512 * 256];
__device__ float    g_btrel[RR * 128 * 256];
__device__ float    g_btfus[128 * 640];

__device__ __forceinline__ float lrelu(float v) { return v > 0.f ? v : 0.2f * v; }

__device__ __forceinline__ unsigned f2tf32(float f) {
    unsigned r;
    asm("cvt.rna.tf32.f32 %0, %1;" : "=r"(r) : "f"(f));
    return r;
}
__device__ __forceinline__ float rtf(float f) { return __uint_as_float(f2tf32(f)); }

__device__ __forceinline__ void cp16(unsigned sm, const void* gm) {
    asm volatile("cp.async.cg.shared.global [%0], [%1], 16;" :: "r"(sm), "l"(gm));
}
__device__ __forceinline__ void cpcommit() {
    asm volatile("cp.async.commit_group;");
}
template <int N>
__device__ __forceinline__ void cpwait() {
    asm volatile("cp.async.wait_group %0;" :: "n"(N));
}

// ---------------- zero / counts / scan / fill ----------------
__global__ void k_zero_small() {
    int i = blockIdx.x * blockDim.x + threadIdx.x;
    if (i < NN) { g_deg[i] = 0; g_cursor[i] = 0; }
    if (i < NN * RR) g_cnt4[i] = 0;
}

__global__ void k_count(const int* __restrict__ dst, const int* __restrict__ et) {
    int i = blockIdx.x * blockDim.x + threadIdx.x;
    if (i >= EE) return;
    int d = dst[i];
    atomicAdd(&g_deg[d], 1);
    atomicAdd(&g_cnt4[d * RR + et[i]], 1);
}

__global__ void k_scan1() {
    __shared__ int sh[256];
    int b = blockIdx.x, t = threadIdx.x;
    int i = b * 256 + t;
    int v = (i < NN) ? g_deg[i] : 0;
    sh[t] = v; __syncthreads();
    for (int o = 1; o < 256; o <<= 1) {
        int add = (t >= o) ? sh[t - o] : 0;
        __syncthreads();
        sh[t] += add;
        __syncthreads();
    }
    if (i < NN) g_rowstart[i] = sh[t] - v;
    if (t == 255) g_bsum[b] = sh[255];
}

__global__ void k_scan2() {
    __shared__ int sh[256];
    int t = threadIdx.x;
    int v = (t < NBLK) ? g_bsum[t] : 0;
    sh[t] = v; __syncthreads();
    for (int o = 1; o < 256; o <<= 1) {
        int add = (t >= o) ? sh[t - o] : 0;
        __syncthreads();
        sh[t] += add;
        __syncthreads();
    }
    g_boff[t] = sh[t] - v;
}

__global__ void k_scan3_inv() {
    int i = blockIdx.x * blockDim.x + threadIdx.x;
    if (i >= NN) return;
    g_rowstart[i] += g_boff[i >> 8];
    g_invdeg[i] = 1.f / fmaxf((float)g_deg[i], 1.f);
#pragma unroll
    for (int r = 0; r < RR; r++)
        g_invcnt4[i * RR + r] = 1.f / fmaxf((float)g_cnt4[i * RR + r], 1.f);
}

__global__ void k_fill(const int* __restrict__ src, const int* __restrict__ dst,
                       const int* __restrict__ et) {
    int e = blockIdx.x * blockDim.x + threadIdx.x;
    if (e >= EE) return;
    int d = dst[e];
    int pos = atomicAdd(&g_cursor[d], 1);
    int slot = g_rowstart[d] + pos;
    g_es[slot] = src[e];
    g_etl[slot] = et[e];
}

// ---------------- weight transpose (+tf32 round) ----------------
struct TSeg { const float* B; float* Bt; int K; int N; int ldBt; int kOff; };
struct TSegs { TSeg s[11]; };

__global__ void k_transAll(TSegs P) {
    TSeg sg = P.s[blockIdx.y];
    int i = blockIdx.x * blockDim.x + threadIdx.x;
    if (i >= sg.K * sg.N) return;
    int k = i / sg.N, n = i % sg.N;
    sg.Bt[(size_t)n * sg.ldBt + sg.kOff + k] = rtf(sg.B[(size_t)k * sg.N + n]);
}

__global__ void k_round4(const float4* __restrict__ in, float4* __restrict__ out, int n4) {
    int i = blockIdx.x * blockDim.x + threadIdx.x;
    if (i >= n4) return;
    float4 v = in[i];
    v.x = rtf(v.x); v.y = rtf(v.y); v.z = rtf(v.z); v.w = rtf(v.w);
    out[i] = v;
}

// ---------------- SAGE mean-gather: 4 edge-groups x (D/4) float4 lanes (R8 form) ----------------
template <int D>
__global__ __launch_bounds__(D) void k_sage_gather(const float* __restrict__ xin,
                                                   float* __restrict__ agg) {
    constexpr int L = D / 4;
    __shared__ float4 sred[4][L];
    int n = blockIdx.x;
    int tid = threadIdx.x;
    int grp = tid / L, lane = tid % L;
    int base = g_rowstart[n], deg = g_deg[n];
    const float4* xin4 = (const float4*)xin;
    float4 acc = make_float4(0.f, 0.f, 0.f, 0.f);
    for (int j = grp; j < deg; j += 4) {
        int s = g_es[base + j];
        float4 v = xin4[(size_t)s * L + lane];
        acc.x += v.x; acc.y += v.y; acc.z += v.z; acc.w += v.w;
    }
    sred[grp][lane] = acc;
    __syncthreads();
    if (grp == 0) {
        float4 a = sred[0][lane], b = sred[1][lane], c = sred[2][lane], d = sred[3][lane];
        float w = g_invdeg[n];
        float4 o;
        o.x = rtf((a.x + b.x + c.x + d.x) * w);
        o.y = rtf((a.y + b.y + c.y + d.y) * w);
        o.z = rtf((a.z + b.z + c.z + d.z) * w);
        o.w = rtf((a.w + b.w + c.w + d.w) * w);
        ((float4*)agg)[(size_t)n * L + lane] = o;
    }
}

// ---------------- TF32 GEMM: 128x128, 4-stage cp.async pipeline, 1 sync/tile (R8) ----------------
__global__ __launch_bounds__(256) void tgemm(
    const float* __restrict__ A0, int K0,
    const float* __restrict__ A1, int K1,
    const float* __restrict__ A2, int K2,
    const float* __restrict__ Bt,
    float* __restrict__ C, const float* __restrict__ bias,
    int M, int Nc, int accFlag, int reluFlag, int roundFlag,
    size_t zsB, size_t zsC) {
    extern __shared__ float sm[];
    float* smA = sm;               // 4 * 2560 floats
    float* smB = sm + 4 * 2560;
#define ASX(st, r, c) smA[(st) * 2560 + (r) * 20 + (c)]
#define BSX(st, r, c) smB[(st) * 2560 + (r) * 20 + (c)]
    const int tid = threadIdx.x;
    const int m0 = blockIdx.y * 128, n0 = blockIdx.x * 128;
    const int wid = tid >> 5, lane = tid & 31;
    const int wm = wid & 3, wn = wid >> 2;
    const int g = lane >> 2, tq = lane & 3;
    const int Ktot = K0 + K1 + K2;
    Bt += blockIdx.z * zsB;
    C  += blockIdx.z * zsC;
    const float* segA[3] = {A0, A1, A2};
    const int segK01 = K0 + K1;
    const int T = Ktot >> 4;

    float acc[2][8][4];
#pragma unroll
    for (int mt = 0; mt < 2; mt++)
#pragma unroll
        for (int nt = 0; nt < 8; nt++)
#pragma unroll
            for (int r = 0; r < 4; r++) acc[mt][nt][r] = 0.f;

    const int aRow = tid >> 1;
    const int aCol = (tid & 1) * 8;
    const bool aValid = (m0 + aRow) < M;
    const int aR = aValid ? (m0 + aRow) : 0;
    const float* BtRow = Bt + (size_t)(n0 + aRow) * Ktot + aCol;

    const int aLr = (lane & 7) + (((lane >> 3) & 1) << 3);
    const int aLc = ((lane >> 4) & 1) * 4;
    const int bLr = (lane & 7) + (((lane >> 4) & 1) << 3);
    const int bLc = ((lane >> 3) & 1) * 4;

    auto issue = [&](int tile, int buf) {
        int kpos = tile * 16;
        int s, kk;
        if (kpos < K0) { s = 0; kk = kpos; }
        else if (kpos < segK01) { s = 1; kk = kpos - K0; }
        else { s = 2; kk = kpos - segK01; }
        int Ks = (s == 0) ? K0 : (s == 1) ? K1 : K2;
        const float* Ag = segA[s] + (size_t)aR * Ks + kk + aCol;
        unsigned sa = (unsigned)__cvta_generic_to_shared(&ASX(buf, aRow, aCol));
        cp16(sa, Ag); cp16(sa + 16, Ag + 4);
        const float* Bg = BtRow + kpos;
        unsigned sb = (unsigned)__cvta_generic_to_shared(&BSX(buf, aRow, aCol));
        cp16(sb, Bg); cp16(sb + 16, Bg + 4);
    };

    for (int p = 0; p < 3 && p < T; p++) { issue(p, p); cpcommit(); }

    for (int t = 0; t < T; t++) {
        cpwait<2>();
        __syncthreads();
        if (t + 3 < T) issue(t + 3, (t + 3) & 3);
        cpcommit();
        const int pb = t & 3;
#pragma unroll
        for (int ks = 0; ks < 16; ks += 8) {
            unsigned af[2][4], bf[4][4];
#pragma unroll
            for (int mt = 0; mt < 2; mt++) {
                unsigned addr = (unsigned)__cvta_generic_to_shared(
                    &ASX(pb, wm * 32 + mt * 16 + aLr, ks + aLc));
                asm volatile("ldmatrix.sync.aligned.m8n8.x4.shared.b16 {%0,%1,%2,%3}, [%4];"
                    : "=r"(af[mt][0]), "=r"(af[mt][1]), "=r"(af[mt][2]), "=r"(af[mt][3])
                    : "r"(addr));
            }
#pragma unroll
            for (int np = 0; np < 4; np++) {
                unsigned addr = (unsigned)__cvta_generic_to_shared(
                    &BSX(pb, wn * 64 + np * 16 + bLr, ks + bLc));
                asm volatile("ldmatrix.sync.aligned.m8n8.x4.shared.b16 {%0,%1,%2,%3}, [%4];"
                    : "=r"(bf[np][0]), "=r"(bf[np][1]), "=r"(bf[np][2]), "=r"(bf[np][3])
                    : "r"(addr));
            }
#pragma unroll
            for (int mt = 0; mt < 2; mt++)
#pragma unroll
                for (int nt = 0; nt < 8; nt++) {
                    unsigned b0 = bf[nt >> 1][(nt & 1) * 2 + 0];
                    unsigned b1 = bf[nt >> 1][(nt & 1) * 2 + 1];
                    float* c = acc[mt][nt];
                    asm volatile(
                        "mma.sync.aligned.m16n8k8.row.col.f32.tf32.tf32.f32 "
                        "{%0,%1,%2,%3}, {%4,%5,%6,%7}, {%8,%9}, {%0,%1,%2,%3};"
                        : "+f"(c[0]), "+f"(c[1]), "+f"(c[2]), "+f"(c[3])
                        : "r"(af[mt][0]), "r"(af[mt][1]), "r"(af[mt][2]), "r"(af[mt][3]),
                          "r"(b0), "r"(b1));
                }
        }
    }

#pragma unroll
    for (int mt = 0; mt < 2; mt++) {
        int r0 = m0 + wm * 32 + mt * 16 + g;
#pragma unroll
        for (int half = 0; half < 2; half++) {
            int row = r0 + half * 8;
            if (row >= M) continue;
#pragma unroll
            for (int nt = 0; nt < 8; nt++) {
                int col = n0 + wn * 64 + nt * 8 + 2 * tq;
                float* p = C + (size_t)row * Nc + col;
                float2 cv;
                cv.x = acc[mt][nt][half * 2 + 0];
                cv.y = acc[mt][nt][half * 2 + 1];
                if (accFlag) { float2 o = *(const float2*)p; cv.x += o.x; cv.y += o.y; }
                if (bias != nullptr) { cv.x += bias[col]; cv.y += bias[col + 1]; }
                if (reluFlag) { cv.x = fmaxf(cv.x, 0.f); cv.y = fmaxf(cv.y, 0.f); }
                if (roundFlag) { cv.x = rtf(cv.x); cv.y = rtf(cv.y); }
                *(float2*)p = cv;
            }
        }
    }
#undef ASX
#undef BSX
}

// ---------------- GAT: per-node attention logits (float4) ----------------
__global__ __launch_bounds__(256) void k_al(const float* __restrict__ aS,
                                            const float* __restrict__ aD) {
    int gw = (int)(((size_t)blockIdx.x * blockDim.x + threadIdx.x) >> 5);
    int lane = threadIdx.x & 31;
    if (gw >= NN * 2) return;
    int n = gw >> 1, k = gw & 1;
    const float4* hp = (const float4*)(g_h + (size_t)n * 512 + k * 256);
    const float4* as4 = (const float4*)(aS + k * 256);
    const float4* ad4 = (const float4*)(aD + k * 256);
    float ss = 0.f, sd = 0.f;
#pragma unroll
    for (int it = 0; it < 2; it++) {
        int j = lane + it * 32;
        float4 h = hp[j], A = as4[j], D = ad4[j];
        ss += h.x * A.x + h.y * A.y + h.z * A.z + h.w * A.w;
        sd += h.x * D.x + h.y * D.y + h.z * D.z + h.w * D.w;
    }
#pragma unroll
    for (int o = 16; o; o >>= 1) {
        ss += __shfl_down_sync(0xffffffffu, ss, o);
        sd += __shfl_down_sync(0xffffffffu, sd, o);
    }
    if (lane == 0) { g_als[gw] = ss; g_ald[gw] = sd; }
}

// ---------------- GAT: online-softmax, thread owns float2 of features ----------------
__global__ __launch_bounds__(256) void k_gat(const float* __restrict__ bias) {
    __shared__ float sW0[256], sW1[256];
    __shared__ int   sS[256];
    __shared__ float wm0[8], wm1[8];
    __shared__ float2 stage[128];
    int n = blockIdx.x;
    int t = threadIdx.x;
    int lane = t & 31, warp = t >> 5;
    int base = g_rowstart[n], deg = g_deg[n];

    float ald0 = g_ald[2 * n], ald1 = g_ald[2 * n + 1];
    float m0 = lrelu(g_als[2 * n] + ald0);
    float m1 = lrelu(g_als[2 * n + 1] + ald1);
    float d0 = 1.f, d1 = 1.f;
    const float2* h2 = (const float2*)g_h;
    float2 a = h2[(size_t)n * 256 + t];
    bool head0 = (t < 128);

    for (int c0 = 0; c0 < deg; c0 += 256) {
        int cnt = min(256, deg - c0);
        float e0 = -1e30f, e1 = -1e30f;
        int sNode = 0;
        if (t < cnt) {
            sNode = g_es[base + c0 + t];
            e0 = lrelu(g_als[2 * sNode] + ald0);
            e1 = lrelu(g_als[2 * sNode + 1] + ald1);
        }
        float w0r = e0, w1r = e1;
#pragma unroll
        for (int o = 16; o; o >>= 1) {
            w0r = fmaxf(w0r, __shfl_xor_sync(0xffffffffu, w0r, o));
            w1r = fmaxf(w1r, __shfl_xor_sync(0xffffffffu, w1r, o));
        }
        if (lane == 0) { wm0[warp] = w0r; wm1[warp] = w1r; }
        __syncthreads();
        float cm0 = wm0[0], cm1 = wm1[0];
#pragma unroll
        for (int w = 1; w < 8; w++) { cm0 = fmaxf(cm0, wm0[w]); cm1 = fmaxf(cm1, wm1[w]); }

        float M0 = fmaxf(m0, cm0), M1 = fmaxf(m1, cm1);
        float sc0 = expf(m0 - M0), sc1 = expf(m1 - M1);
        float scMe = head0 ? sc0 : sc1;
        a.x *= scMe; a.y *= scMe;
        d0 *= sc0; d1 *= sc1; m0 = M0; m1 = M1;

        if (t < cnt) {
            sS[t] = sNode;
            sW0[t] = expf(e0 - m0);
            sW1[t] = expf(e1 - m1);
        }
        __syncthreads();
        for (int j = 0; j < cnt; j++) {
            float w0 = sW0[j], w1 = sW1[j];
            float w = head0 ? w0 : w1;
            float2 hv = h2[(size_t)sS[j] * 256 + t];
            a.x += w * hv.x; a.y += w * hv.y;
            d0 += w0; d1 += w1;
        }
        __syncthreads();
    }
    float i0 = 1.f / fmaxf(d0, 1e-16f), i1 = 1.f / fmaxf(d1, 1e-16f);
    if (!head0) stage[t - 128] = a;
    __syncthreads();
    if (head0) {
        float2 b1 = stage[t];
        float v0 = 0.5f * (a.x * i0 + b1.x * i1) + bias[2 * t];
        float v1 = 0.5f * (a.y * i0 + b1.y * i1) + bias[2 * t + 1];
        float2 o;
        o.x = rtf(fmaxf(v0, 0.f));
        o.y = rtf(fmaxf(v1, 0.f));
        ((float2*)g_xgat)[(size_t)n * 128 + t] = o;
    }
}

// ---------------- RGCN gather: 4 edge-groups x 32 float4 lanes (R8 form) ----------------
__global__ __launch_bounds__(128) void k_rgcn() {
    __shared__ float4 sred[4][32];
    int n = blockIdx.x;
    int t = threadIdx.x;
    int grp = t >> 5, lane = t & 31;
    int base = g_rowstart[n], deg = g_deg[n];
    float w0 = g_invcnt4[n * 4 + 0], w1 = g_invcnt4[n * 4 + 1];
    float w2 = g_invcnt4[n * 4 + 2], w3 = g_invcnt4[n * 4 + 3];
    const float4* xt4 = (const float4*)g_xt;
    float4 acc = make_float4(0.f, 0.f, 0.f, 0.f);
    for (int j = grp; j < deg; j += 4) {
        int s = g_es[base + j];
        int r = g_etl[base + j];
        float w = (r == 0) ? w0 : (r == 1) ? w1 : (r == 2) ? w2 : w3;
        float4 v = xt4[((size_t)r * NN + s) * 32 + lane];
        acc.x += w * v.x; acc.y += w * v.y; acc.z += w * v.z; acc.w += w * v.w;
    }
    sred[grp][lane] = acc;
    __syncthreads();
    if (grp == 0) {
        float4 A = sred[0][lane], B = sred[1][lane], C = sred[2][lane], D = sred[3][lane];
        float4 o;
        o.x = rtf(A.x + B.x + C.x + D.x);
        o.y = rtf(A.y + B.y + C.y + D.y);
        o.z = rtf(A.z + B.z + C.z + D.z);
        o.w = rtf(A.w + B.w + C.w + D.w);
        ((float4*)g_xrgcn)[(size_t)n * 32 + lane] = o;
    }
}

// ---------------- fold rgcn root into fusion weights ----------------
__global__ void k_compose(const float* __restrict__ fW, const float* __restrict__ fB,
                          const float* __restrict__ Wroot, const float* __restrict__ rgcB,
                          float* __restrict__ btfus) {
    int b = blockIdx.x, t = threadIdx.x;
    const float* F3 = fW + 512 * EMBD;
    if (b < HID) {
        float acc = fW[(256 + b) * EMBD + t];
        for (int h = 0; h < EMBD; h++)
            acc += Wroot[b * EMBD + h] * F3[h * EMBD + t];
        btfus[(size_t)t * 640 + 256 + b] = rtf(acc);
    } else {
        float acc = fB[t];
        for (int h = 0; h < EMBD; h++)
            acc += rgcB[h] * F3[h * EMBD + t];
        g_fb2[t] = acc;
    }
}

// ---------------- final L2 normalize ----------------
__global__ void k_norm(float* __restrict__ out) {
    int n = blockIdx.x;
    int t = threadIdx.x;
    float v = out[(size_t)n * EMBD + t];
    float s = v * v;
#pragma unroll
    for (int o = 16; o; o >>= 1) s += __shfl_down_sync(0xffffffffu, s, o);
    __shared__ float sh[4];
    if ((t & 31) == 0) sh[t >> 5] = s;
    __syncthreads();
    float tot = sh[0] + sh[1] + sh[2] + sh[3];
    float nrm = fmaxf(sqrtf(tot), 1e-12f);
    out[(size_t)n * EMBD + t] = v / nrm;
}

// ---------------- host ----------------
#define TG_SMEM (4 * 2 * 2560 * 4)

static void launch_seg(const float* A0, int K0, const float* A1, int K1,
                       const float* A2, int K2, const float* Bt,
                       float* C, const float* bias, int M, int Nc,
                       int acc, int relu, int rnd,
                       int gz = 1, size_t zsB = 0, size_t zsC = 0) {
    dim3 grid(Nc / 128, (M + 127) / 128, gz);
    tgemm<<<grid, 256, TG_SMEM>>>(A0, K0, A1, K1, A2, K2, Bt, C, bias, M, Nc,
                                  acc, relu, rnd, zsB, zsC);
}

extern "C" void kernel_launch(void* const* d_in, const int* in_sizes, int n_in,
                              void* d_out, int out_size) {
    const float* x    = (const float*)d_in[0];
    const int*   ei   = (const int*)d_in[1];
    const int*   et   = (const int*)d_in[2];
    const float* s1Wl = (const float*)d_in[3];
    const float* s1Wr = (const float*)d_in[4];
    const float* s1b  = (const float*)d_in[5];
    const float* s2Wl = (const float*)d_in[6];
    const float* s2Wr = (const float*)d_in[7];
    const float* s2b  = (const float*)d_in[8];
    const float* gatW = (const float*)d_in[9];
    const float* aSrc = (const float*)d_in[10];
    const float* aDst = (const float*)d_in[11];
    const float* gatB = (const float*)d_in[12];
    const float* Wrel = (const float*)d_in[13];
    const float* Wroot= (const float*)d_in[14];
    const float* rgcB = (const float*)d_in[15];
    const float* fW   = (const float*)d_in[16];
    const float* fB   = (const float*)d_in[17];
    float* out = (float*)d_out;

    const int* src = ei;
    const int* dst = ei + EE;

    cudaFuncSetAttribute(tgemm, cudaFuncAttributeMaxDynamicSharedMemorySize, TG_SMEM);

    float *p_xr, *p_agg1, *p_x1, *p_agg2, *p_xsage, *p_h, *p_xgat, *p_xt, *p_xrgcn, *p_fb2;
    float *p_bt1, *p_bt2, *p_btg, *p_btrel, *p_btfus;
    cudaGetSymbolAddress((void**)&p_xr, g_xr);
    cudaGetSymbolAddress((void**)&p_agg1, g_agg1);
    cudaGetSymbolAddress((void**)&p_x1, g_x1);
    cudaGetSymbolAddress((void**)&p_agg2, g_agg2);
    cudaGetSymbolAddress((void**)&p_xsage, g_xsage);
    cudaGetSymbolAddress((void**)&p_h, g_h);
    cudaGetSymbolAddress((void**)&p_xgat, g_xgat);
    cudaGetSymbolAddress((void**)&p_xt, g_xt);
    cudaGetSymbolAddress((void**)&p_xrgcn, g_xrgcn);
    cudaGetSymbolAddress((void**)&p_fb2, g_fb2);
    cudaGetSymbolAddress((void**)&p_bt1, g_bt1);
    cudaGetSymbolAddress((void**)&p_bt2, g_bt2);
    cudaGetSymbolAddress((void**)&p_btg, g_btg);
    cudaGetSymbolAddress((void**)&p_btrel, g_btrel);
    cudaGetSymbolAddress((void**)&p_btfus, g_btfus);

    // ---- setup + CSR build ----
    k_zero_small<<<(NN * RR + 255) / 256, 256>>>();
    k_count<<<(EE + 255) / 256, 256>>>(dst, et);
    k_round4<<<(NN * IN_C / 4 + 255) / 256, 256>>>((const float4*)x, (float4*)p_xr,
                                                   NN * IN_C / 4);
    k_scan1<<<NBLK, 256>>>();
    k_scan2<<<1, 256>>>();
    k_scan3_inv<<<NBLK, 256>>>();
    k_fill<<<(EE + 255) / 256, 256>>>(src, dst, et);

    // all weight transposes in ONE launch (incl. stacked SAGE1)
    TSegs ts;
    ts.s[0]  = {s1Wl, p_bt1, 128, 256, 256, 0};
    ts.s[1]  = {s1Wr, p_bt1, 128, 256, 256, 128};
    ts.s[2]  = {s2Wl, p_bt2, 256, 256, 512, 0};
    ts.s[3]  = {s2Wr, p_bt2, 256, 256, 512, 256};
    ts.s[4]  = {gatW, p_btg, 256, 512, 256, 0};
    ts.s[5]  = {Wrel + 0 * (size_t)HID * EMBD, p_btrel + 0 * (size_t)128 * 256, 256, 128, 256, 0};
    ts.s[6]  = {Wrel + 1 * (size_t)HID * EMBD, p_btrel + 1 * (size_t)128 * 256, 256, 128, 256, 0};
    ts.s[7]  = {Wrel + 2 * (size_t)HID * EMBD, p_btrel + 2 * (size_t)128 * 256, 256, 128, 256, 0};
    ts.s[8]  = {Wrel + 3 * (size_t)HID * EMBD, p_btrel + 3 * (size_t)128 * 256, 256, 128, 256, 0};
    ts.s[9]  = {fW, p_btfus, 256, 128, 640, 0};
    ts.s[10] = {fW + 512 * EMBD, p_btfus, 128, 128, 640, 512};
    k_transAll<<<dim3(512, 11), 256>>>(ts);
    k_compose<<<HID + 1, EMBD>>>(fW, fB, Wroot, rgcB, p_btfus);

    // ---- SAGE 1 (single fused dual-A GEMM) ----
    k_sage_gather<IN_C><<<NN, IN_C>>>(x, p_agg1);
    launch_seg(p_agg1, IN_C, p_xr, IN_C, 0, 0, p_bt1, p_x1, s1b, NN, HID, 0, 1, 1);

    // ---- SAGE 2 (fused dual-A GEMM) ----
    k_sage_gather<HID><<<NN, HID>>>(p_x1, p_agg2);
    launch_seg(p_agg2, HID, p_x1, HID, 0, 0, p_bt2, p_xsage, s2b, NN, HID, 0, 1, 1);

    // ---- GAT ----
    launch_seg(p_xsage, HID, 0, 0, 0, 0, p_btg, p_h, nullptr, NN, 2 * HID, 0, 0, 0);
    k_al<<<(NN * 2 * 32 + 255) / 256, 256>>>(aSrc, aDst);
    k_gat<<<NN, 256>>>(gatB);

    // ---- RGCN (4 relations via grid.z) ----
    launch_seg(p_xgat, HID, 0, 0, 0, 0, p_btrel, p_xt, nullptr, NN, EMBD, 0, 0, 0,
               RR, (size_t)128 * 256, (size_t)NN * EMBD);
    k_rgcn<<<NN, 128>>>();

    // ---- Fusion (3-segment, rgcn-root folded) + normalize ----
    launch_seg(p_xsage, HID, p_xgat, HID, p_xrgcn, EMBD, p_btfus,
               out, p_fb2, NN, EMBD, 0, 0, 0);
    k_norm<<<NN, 128>>>(out);
}

// round 15
// speedup vs baseline: 1.4475x; 1.2228x over previous
#include <cuda_runtime.h>
#include <cuda_fp16.h>
#include <math.h>

#define NN   50000
#define EE   800000
#define IN_C 128
#define HID  256
#define EMBD 128
#define RR   4
#define NBLK ((NN + 255) / 256)

// ---------------- scratch (device globals; no allocation) ----------------
__device__ int      g_deg[NN];
__device__ float    g_invdeg[NN];
__device__ int      g_cnt4[NN * RR];
__device__ float    g_invcnt4[NN * RR];
__device__ int      g_rowstart[NN];
__device__ int      g_cursor[NN];
__device__ int      g_bsum[256];
__device__ int      g_boff[256];
__device__ int      g_es[EE];
__device__ int      g_etl[EE];
__device__ float    g_h[(size_t)NN * 2 * HID];
__device__ float    g_als[NN * 2];
__device__ float    g_ald[NN * 2];
__device__ float    g_xt[(size_t)RR * NN * EMBD];
__device__ float    g_fb2[EMBD];
// fp16 GEMM inputs
__device__ __align__(16) __half g_xrh[(size_t)NN * IN_C];
__device__ __align__(16) __half g_agg1h[(size_t)NN * IN_C];
__device__ __align__(16) __half g_x1h[(size_t)NN * HID];
__device__ __align__(16) __half g_agg2h[(size_t)NN * HID];
__device__ __align__(16) __half g_xsageh[(size_t)NN * HID];
__device__ __align__(16) __half g_xgath[(size_t)NN * HID];
__device__ __align__(16) __half g_xrgcnh[(size_t)NN * EMBD];
// fp16 pre-transposed weights Bt[n][k]
__device__ __align__(16) __half g_bt1[256 * 256];
__device__ __align__(16) __half g_bt2[256 * 512];
__device__ __align__(16) __half g_btg[512 * 256];
__device__ __align__(16) __half g_btrel[RR * 128 * 256];
__device__ __align__(16) __half g_btfus[128 * 640];

__device__ __forceinline__ float lrelu(float v) { return v > 0.f ? v : 0.2f * v; }

__device__ __forceinline__ void cp16(unsigned sm, const void* gm) {
    asm volatile("cp.async.cg.shared.global [%0], [%1], 16;" :: "r"(sm), "l"(gm));
}
__device__ __forceinline__ void cpcommit() {
    asm volatile("cp.async.commit_group;");
}
template <int N>
__device__ __forceinline__ void cpwait() {
    asm volatile("cp.async.wait_group %0;" :: "n"(N));
}

// ---------------- zero / counts / scan / fill ----------------
__global__ void k_zero_small() {
    int i = blockIdx.x * blockDim.x + threadIdx.x;
    if (i < NN) { g_deg[i] = 0; g_cursor[i] = 0; }
    if (i < NN * RR) g_cnt4[i] = 0;
}

__global__ void k_count(const int* __restrict__ dst, const int* __restrict__ et) {
    int i = blockIdx.x * blockDim.x + threadIdx.x;
    if (i >= EE) return;
    int d = dst[i];
    atomicAdd(&g_deg[d], 1);
    atomicAdd(&g_cnt4[d * RR + et[i]], 1);
}

__global__ void k_scan1() {
    __shared__ int sh[256];
    int b = blockIdx.x, t = threadIdx.x;
    int i = b * 256 + t;
    int v = (i < NN) ? g_deg[i] : 0;
    sh[t] = v; __syncthreads();
    for (int o = 1; o < 256; o <<= 1) {
        int add = (t >= o) ? sh[t - o] : 0;
        __syncthreads();
        sh[t] += add;
        __syncthreads();
    }
    if (i < NN) g_rowstart[i] = sh[t] - v;
    if (t == 255) g_bsum[b] = sh[255];
}

__global__ void k_scan2() {
    __shared__ int sh[256];
    int t = threadIdx.x;
    int v = (t < NBLK) ? g_bsum[t] : 0;
    sh[t] = v; __syncthreads();
    for (int o = 1; o < 256; o <<= 1) {
        int add = (t >= o) ? sh[t - o] : 0;
        __syncthreads();
        sh[t] += add;
        __syncthreads();
    }
    g_boff[t] = sh[t] - v;
}

__global__ void k_scan3_inv() {
    int i = blockIdx.x * blockDim.x + threadIdx.x;
    if (i >= NN) return;
    g_rowstart[i] += g_boff[i >> 8];
    g_invdeg[i] = 1.f / fmaxf((float)g_deg[i], 1.f);
#pragma unroll
    for (int r = 0; r < RR; r++)
        g_invcnt4[i * RR + r] = 1.f / fmaxf((float)g_cnt4[i * RR + r], 1.f);
}

__global__ void k_fill(const int* __restrict__ src, const int* __restrict__ dst,
                       const int* __restrict__ et) {
    int e = blockIdx.x * blockDim.x + threadIdx.x;
    if (e >= EE) return;
    int d = dst[e];
    int pos = atomicAdd(&g_cursor[d], 1);
    int slot = g_rowstart[d] + pos;
    g_es[slot] = src[e];
    g_etl[slot] = et[e];
}

// ---------------- weight transpose -> fp16 ----------------
struct TSeg { const float* B; __half* Bt; int K; int N; int ldBt; int kOff; };
struct TSegs { TSeg s[11]; };

__global__ void k_transAll(TSegs P) {
    TSeg sg = P.s[blockIdx.y];
    int i = blockIdx.x * blockDim.x + threadIdx.x;
    if (i >= sg.K * sg.N) return;
    int k = i / sg.N, n = i % sg.N;
    sg.Bt[(size_t)n * sg.ldBt + sg.kOff + k] = __float2half_rn(sg.B[(size_t)k * sg.N + n]);
}

__global__ void k_round_h(const float4* __restrict__ in, __half2* __restrict__ out, int n4) {
    int i = blockIdx.x * blockDim.x + threadIdx.x;
    if (i >= n4) return;
    float4 v = in[i];
    out[i * 2 + 0] = __floats2half2_rn(v.x, v.y);
    out[i * 2 + 1] = __floats2half2_rn(v.z, v.w);
}

// ---------------- SAGE mean-gather (float input) ----------------
template <int D>
__global__ __launch_bounds__(D) void k_sage_gather_f(const float* __restrict__ xin,
                                                     __half* __restrict__ agg) {
    constexpr int L = D / 4;
    __shared__ float4 sred[4][L];
    int n = blockIdx.x;
    int tid = threadIdx.x;
    int grp = tid / L, lane = tid % L;
    int base = g_rowstart[n], deg = g_deg[n];
    const float4* xin4 = (const float4*)xin;
    float4 acc = make_float4(0.f, 0.f, 0.f, 0.f);
    for (int j = grp; j < deg; j += 4) {
        int s = g_es[base + j];
        float4 v = xin4[(size_t)s * L + lane];
        acc.x += v.x; acc.y += v.y; acc.z += v.z; acc.w += v.w;
    }
    sred[grp][lane] = acc;
    __syncthreads();
    if (grp == 0) {
        float4 a = sred[0][lane], b = sred[1][lane], c = sred[2][lane], d = sred[3][lane];
        float w = g_invdeg[n];
        __half2* o2 = (__half2*)agg + ((size_t)n * L + lane) * 2;
        o2[0] = __floats2half2_rn((a.x + b.x + c.x + d.x) * w, (a.y + b.y + c.y + d.y) * w);
        o2[1] = __floats2half2_rn((a.z + b.z + c.z + d.z) * w, (a.w + b.w + c.w + d.w) * w);
    }
}

// ---------------- SAGE mean-gather (half input) ----------------
template <int D>
__global__ __launch_bounds__(D) void k_sage_gather_h(const __half* __restrict__ xin,
                                                     __half* __restrict__ agg) {
    constexpr int L = D / 4;
    __shared__ float4 sred[4][L];
    int n = blockIdx.x;
    int tid = threadIdx.x;
    int grp = tid / L, lane = tid % L;
    int base = g_rowstart[n], deg = g_deg[n];
    const __half2* xin2 = (const __half2*)xin;
    float4 acc = make_float4(0.f, 0.f, 0.f, 0.f);
    for (int j = grp; j < deg; j += 4) {
        int s = g_es[base + j];
        size_t p = ((size_t)s * L + lane) * 2;
        float2 f0 = __half22float2(xin2[p]);
        float2 f1 = __half22float2(xin2[p + 1]);
        acc.x += f0.x; acc.y += f0.y; acc.z += f1.x; acc.w += f1.y;
    }
    sred[grp][lane] = acc;
    __syncthreads();
    if (grp == 0) {
        float4 a = sred[0][lane], b = sred[1][lane], c = sred[2][lane], d = sred[3][lane];
        float w = g_invdeg[n];
        __half2* o2 = (__half2*)agg + ((size_t)n * L + lane) * 2;
        o2[0] = __floats2half2_rn((a.x + b.x + c.x + d.x) * w, (a.y + b.y + c.y + d.y) * w);
        o2[1] = __floats2half2_rn((a.z + b.z + c.z + d.z) * w, (a.w + b.w + c.w + d.w) * w);
    }
}

// ---------------- FP16 GEMM: 128x128 tile, K-tile 32, 4-stage cp.async, 1 sync/tile ----------------
// C[M,Nc] = sum_s A_s[M,K_s] @ Bt^T   (half inputs, fp32 accum; halfOut selects C type)
__global__ __launch_bounds__(256) void tgemm(
    const __half* __restrict__ A0, int K0,
    const __half* __restrict__ A1, int K1,
    const __half* __restrict__ A2, int K2,
    const __half* __restrict__ Bt,
    void* __restrict__ Cv, const float* __restrict__ bias,
    int M, int Nc, int reluFlag, int halfOut,
    size_t zsB, size_t zsC) {
    extern __shared__ __half smh[];
    __half* smA = smh;                 // 4 stages * 128 rows * 40 halves
    __half* smB = smh + 4 * 5120;
#define ASX(st, r, c) smA[(st) * 5120 + (r) * 40 + (c)]
#define BSX(st, r, c) smB[(st) * 5120 + (r) * 40 + (c)]
    const int tid = threadIdx.x;
    const int m0 = blockIdx.y * 128, n0 = blockIdx.x * 128;
    const int wid = tid >> 5, lane = tid & 31;
    const int wm = wid & 3, wn = wid >> 2;
    const int g = lane >> 2, tq = lane & 3;
    const int Ktot = K0 + K1 + K2;
    Bt += blockIdx.z * zsB;
    const __half* segA[3] = {A0, A1, A2};
    const int segK01 = K0 + K1;
    const int T = Ktot >> 5;

    float acc[2][8][4];
#pragma unroll
    for (int mt = 0; mt < 2; mt++)
#pragma unroll
        for (int nt = 0; nt < 8; nt++)
#pragma unroll
            for (int r = 0; r < 4; r++) acc[mt][nt][r] = 0.f;

    const int aRow = tid >> 1;              // 128 rows
    const int aCol = (tid & 1) * 16;        // halves: 0 or 16
    const bool aValid = (m0 + aRow) < M;
    const int aR = aValid ? (m0 + aRow) : 0;
    const __half* BtRow = Bt + (size_t)(n0 + aRow) * Ktot + aCol;

    const int ldR = lane & 15;              // ldmatrix row select
    const int ldC = (lane >> 4) * 8;        // +16B for upper half-warp

    auto issue = [&](int tile, int buf) {
        int kpos = tile * 32;
        int s, kk;
        if (kpos < K0) { s = 0; kk = kpos; }
        else if (kpos < segK01) { s = 1; kk = kpos - K0; }
        else { s = 2; kk = kpos - segK01; }
        int Ks = (s == 0) ? K0 : (s == 1) ? K1 : K2;
        const __half* Ag = segA[s] + (size_t)aR * Ks + kk + aCol;
        unsigned sa = (unsigned)__cvta_generic_to_shared(&ASX(buf, aRow, aCol));
        cp16(sa, Ag); cp16(sa + 16, Ag + 8);
        const __half* Bg = BtRow + kpos;
        unsigned sb = (unsigned)__cvta_generic_to_shared(&BSX(buf, aRow, aCol));
        cp16(sb, Bg); cp16(sb + 16, Bg + 8);
    };

    for (int p = 0; p < 3 && p < T; p++) { issue(p, p); cpcommit(); }

    for (int t = 0; t < T; t++) {
        cpwait<2>();
        __syncthreads();
        if (t + 3 < T) issue(t + 3, (t + 3) & 3);
        cpcommit();
        const int pb = t & 3;
#pragma unroll
        for (int ks = 0; ks < 32; ks += 16) {
            unsigned af[2][4], bf[4][4];
#pragma unroll
            for (int mt = 0; mt < 2; mt++) {
                unsigned addr = (unsigned)__cvta_generic_to_shared(
                    &ASX(pb, wm * 32 + mt * 16 + ldR, ks + ldC));
                asm volatile("ldmatrix.sync.aligned.m8n8.x4.shared.b16 {%0,%1,%2,%3}, [%4];"
                    : "=r"(af[mt][0]), "=r"(af[mt][1]), "=r"(af[mt][2]), "=r"(af[mt][3])
                    : "r"(addr));
            }
#pragma unroll
            for (int np = 0; np < 4; np++) {
                unsigned addr = (unsigned)__cvta_generic_to_shared(
                    &BSX(pb, wn * 64 + np * 16 + ldR, ks + ldC));
                asm volatile("ldmatrix.sync.aligned.m8n8.x4.shared.b16 {%0,%1,%2,%3}, [%4];"
                    : "=r"(bf[np][0]), "=r"(bf[np][1]), "=r"(bf[np][2]), "=r"(bf[np][3])
                    : "r"(addr));
            }
#pragma unroll
            for (int mt = 0; mt < 2; mt++)
#pragma unroll
                for (int nt = 0; nt < 8; nt++) {
                    unsigned b0 = bf[nt >> 1][nt & 1];
                    unsigned b1 = bf[nt >> 1][(nt & 1) + 2];
                    float* c = acc[mt][nt];
                    asm volatile(
                        "mma.sync.aligned.m16n8k16.row.col.f32.f16.f16.f32 "
                        "{%0,%1,%2,%3}, {%4,%5,%6,%7}, {%8,%9}, {%0,%1,%2,%3};"
                        : "+f"(c[0]), "+f"(c[1]), "+f"(c[2]), "+f"(c[3])
                        : "r"(af[mt][0]), "r"(af[mt][1]), "r"(af[mt][2]), "r"(af[mt][3]),
                          "r"(b0), "r"(b1));
                }
        }
    }

    float* Cf = (float*)Cv + blockIdx.z * zsC;
    __half* Ch = (__half*)Cv + blockIdx.z * zsC;
#pragma unroll
    for (int mt = 0; mt < 2; mt++) {
        int r0 = m0 + wm * 32 + mt * 16 + g;
#pragma unroll
        for (int half = 0; half < 2; half++) {
            int row = r0 + half * 8;
            if (row >= M) continue;
#pragma unroll
            for (int nt = 0; nt < 8; nt++) {
                int col = n0 + wn * 64 + nt * 8 + 2 * tq;
                float cx = acc[mt][nt][half * 2 + 0];
                float cy = acc[mt][nt][half * 2 + 1];
                if (bias != nullptr) { cx += bias[col]; cy += bias[col + 1]; }
                if (reluFlag) { cx = fmaxf(cx, 0.f); cy = fmaxf(cy, 0.f); }
                size_t off = (size_t)row * Nc + col;
                if (halfOut) {
                    *(__half2*)(Ch + off) = __floats2half2_rn(cx, cy);
                } else {
                    float2 cv2; cv2.x = cx; cv2.y = cy;
                    *(float2*)(Cf + off) = cv2;
                }
            }
        }
    }
#undef ASX
#undef BSX
}

// ---------------- GAT: per-node attention logits (float4, reads fp32 g_h) ----------------
__global__ __launch_bounds__(256) void k_al(const float* __restrict__ aS,
                                            const float* __restrict__ aD) {
    int gw = (int)(((size_t)blockIdx.x * blockDim.x + threadIdx.x) >> 5);
    int lane = threadIdx.x & 31;
    if (gw >= NN * 2) return;
    int n = gw >> 1, k = gw & 1;
    const float4* hp = (const float4*)(g_h + (size_t)n * 512 + k * 256);
    const float4* as4 = (const float4*)(aS + k * 256);
    const float4* ad4 = (const float4*)(aD + k * 256);
    float ss = 0.f, sd = 0.f;
#pragma unroll
    for (int it = 0; it < 2; it++) {
        int j = lane + it * 32;
        float4 h = hp[j], A = as4[j], D = ad4[j];
        ss += h.x * A.x + h.y * A.y + h.z * A.z + h.w * A.w;
        sd += h.x * D.x + h.y * D.y + h.z * D.z + h.w * D.w;
    }
#pragma unroll
    for (int o = 16; o; o >>= 1) {
        ss += __shfl_down_sync(0xffffffffu, ss, o);
        sd += __shfl_down_sync(0xffffffffu, sd, o);
    }
    if (lane == 0) { g_als[gw] = ss; g_ald[gw] = sd; }
}

// ---------------- GAT: online-softmax, thread owns float2; writes half ----------------
__global__ __launch_bounds__(256) void k_gat(const float* __restrict__ bias) {
    __shared__ float sW0[256], sW1[256];
    __shared__ int   sS[256];
    __shared__ float wm0[8], wm1[8];
    __shared__ float2 stage[128];
    int n = blockIdx.x;
    int t = threadIdx.x;
    int lane = t & 31, warp = t >> 5;
    int base = g_rowstart[n], deg = g_deg[n];

    float ald0 = g_ald[2 * n], ald1 = g_ald[2 * n + 1];
    float m0 = lrelu(g_als[2 * n] + ald0);
    float m1 = lrelu(g_als[2 * n + 1] + ald1);
    float d0 = 1.f, d1 = 1.f;
    const float2* h2 = (const float2*)g_h;
    float2 a = h2[(size_t)n * 256 + t];
    bool head0 = (t < 128);

    for (int c0 = 0; c0 < deg; c0 += 256) {
        int cnt = min(256, deg - c0);
        float e0 = -1e30f, e1 = -1e30f;
        int sNode = 0;
        if (t < cnt) {
            sNode = g_es[base + c0 + t];
            e0 = lrelu(g_als[2 * sNode] + ald0);
            e1 = lrelu(g_als[2 * sNode + 1] + ald1);
        }
        float w0r = e0, w1r = e1;
#pragma unroll
        for (int o = 16; o; o >>= 1) {
            w0r = fmaxf(w0r, __shfl_xor_sync(0xffffffffu, w0r, o));
            w1r = fmaxf(w1r, __shfl_xor_sync(0xffffffffu, w1r, o));
        }
        if (lane == 0) { wm0[warp] = w0r; wm1[warp] = w1r; }
        __syncthreads();
        float cm0 = wm0[0], cm1 = wm1[0];
#pragma unroll
        for (int w = 1; w < 8; w++) { cm0 = fmaxf(cm0, wm0[w]); cm1 = fmaxf(cm1, wm1[w]); }

        float M0 = fmaxf(m0, cm0), M1 = fmaxf(m1, cm1);
        float sc0 = expf(m0 - M0), sc1 = expf(m1 - M1);
        float scMe = head0 ? sc0 : sc1;
        a.x *= scMe; a.y *= scMe;
        d0 *= sc0; d1 *= sc1; m0 = M0; m1 = M1;

        if (t < cnt) {
            sS[t] = sNode;
            sW0[t] = expf(e0 - m0);
            sW1[t] = expf(e1 - m1);
        }
        __syncthreads();
        for (int j = 0; j < cnt; j++) {
            float w0 = sW0[j], w1 = sW1[j];
            float w = head0 ? w0 : w1;
            float2 hv = h2[(size_t)sS[j] * 256 + t];
            a.x += w * hv.x; a.y += w * hv.y;
            d0 += w0; d1 += w1;
        }
        __syncthreads();
    }
    float i0 = 1.f / fmaxf(d0, 1e-16f), i1 = 1.f / fmaxf(d1, 1e-16f);
    if (!head0) stage[t - 128] = a;
    __syncthreads();
    if (head0) {
        float2 b1 = stage[t];
        float v0 = 0.5f * (a.x * i0 + b1.x * i1) + bias[2 * t];
        float v1 = 0.5f * (a.y * i0 + b1.y * i1) + bias[2 * t + 1];
        ((__half2*)g_xgath)[(size_t)n * 128 + t] =
            __floats2half2_rn(fmaxf(v0, 0.f), fmaxf(v1, 0.f));
    }
}

// ---------------- RGCN gather (reads fp32 g_xt, writes half) ----------------
__global__ __launch_bounds__(128) void k_rgcn() {
    __shared__ float4 sred[4][32];
    int n = blockIdx.x;
    int t = threadIdx.x;
    int grp = t >> 5, lane = t & 31;
    int base = g_rowstart[n], deg = g_deg[n];
    float w0 = g_invcnt4[n * 4 + 0], w1 = g_invcnt4[n * 4 + 1];
    float w2 = g_invcnt4[n * 4 + 2], w3 = g_invcnt4[n * 4 + 3];
    const float4* xt4 = (const float4*)g_xt;
    float4 acc = make_float4(0.f, 0.f, 0.f, 0.f);
    for (int j = grp; j < deg; j += 4) {
        int s = g_es[base + j];
        int r = g_etl[base + j];
        float w = (r == 0) ? w0 : (r == 1) ? w1 : (r == 2) ? w2 : w3;
        float4 v = xt4[((size_t)r * NN + s) * 32 + lane];
        acc.x += w * v.x; acc.y += w * v.y; acc.z += w * v.z; acc.w += w * v.w;
    }
    sred[grp][lane] = acc;
    __syncthreads();
    if (grp == 0) {
        float4 A = sred[0][lane], B = sred[1][lane], C = sred[2][lane], D = sred[3][lane];
        __half2* o2 = (__half2*)g_xrgcnh + ((size_t)n * 32 + lane) * 2;
        o2[0] = __floats2half2_rn(A.x + B.x + C.x + D.x, A.y + B.y + C.y + D.y);
        o2[1] = __floats2half2_rn(A.z + B.z + C.z + D.z, A.w + B.w + C.w + D.w);
    }
}

// ---------------- fold rgcn root into fusion weights ----------------
__global__ void k_compose(const float* __restrict__ fW, const float* __restrict__ fB,
                          const float* __restrict__ Wroot, const float* __restrict__ rgcB,
                          __half* __restrict__ btfus) {
    int b = blockIdx.x, t = threadIdx.x;
    const float* F3 = fW + 512 * EMBD;
    if (b < HID) {
        float acc = fW[(256 + b) * EMBD + t];
        for (int h = 0; h < EMBD; h++)
            acc += Wroot[b * EMBD + h] * F3[h * EMBD + t];
        btfus[(size_t)t * 640 + 256 + b] = __float2half_rn(acc);
    } else {
        float acc = fB[t];
        for (int h = 0; h < EMBD; h++)
            acc += rgcB[h] * F3[h * EMBD + t];
        g_fb2[t] = acc;
    }
}

// ---------------- final L2 normalize ----------------
__global__ void k_norm(float* __restrict__ out) {
    int n = blockIdx.x;
    int t = threadIdx.x;
    float v = out[(size_t)n * EMBD + t];
    float s = v * v;
#pragma unroll
    for (int o = 16; o; o >>= 1) s += __shfl_down_sync(0xffffffffu, s, o);
    __shared__ float sh[4];
    if ((t & 31) == 0) sh[t >> 5] = s;
    __syncthreads();
    float tot = sh[0] + sh[1] + sh[2] + sh[3];
    float nrm = fmaxf(sqrtf(tot), 1e-12f);
    out[(size_t)n * EMBD + t] = v / nrm;
}

// ---------------- host ----------------
#define TG_SMEM (4 * 2 * 5120 * 2)

static void launch_seg(const __half* A0, int K0, const __half* A1, int K1,
                       const __half* A2, int K2, const __half* Bt,
                       void* C, const float* bias, int M, int Nc,
                       int relu, int halfOut,
                       int gz = 1, size_t zsB = 0, size_t zsC = 0) {
    dim3 grid(Nc / 128, (M + 127) / 128, gz);
    tgemm<<<grid, 256, TG_SMEM>>>(A0, K0, A1, K1, A2, K2, Bt, C, bias, M, Nc,
                                  relu, halfOut, zsB, zsC);
}

extern "C" void kernel_launch(void* const* d_in, const int* in_sizes, int n_in,
                              void* d_out, int out_size) {
    const float* x    = (const float*)d_in[0];
    const int*   ei   = (const int*)d_in[1];
    const int*   et   = (const int*)d_in[2];
    const float* s1Wl = (const float*)d_in[3];
    const float* s1Wr = (const float*)d_in[4];
    const float* s1b  = (const float*)d_in[5];
    const float* s2Wl = (const float*)d_in[6];
    const float* s2Wr = (const float*)d_in[7];
    const float* s2b  = (const float*)d_in[8];
    const float* gatW = (const float*)d_in[9];
    const float* aSrc = (const float*)d_in[10];
    const float* aDst = (const float*)d_in[11];
    const float* gatB = (const float*)d_in[12];
    const float* Wrel = (const float*)d_in[13];
    const float* Wroot= (const float*)d_in[14];
    const float* rgcB = (const float*)d_in[15];
    const float* fW   = (const float*)d_in[16];
    const float* fB   = (const float*)d_in[17];
    float* out = (float*)d_out;

    const int* src = ei;
    const int* dst = ei + EE;

    cudaFuncSetAttribute(tgemm, cudaFuncAttributeMaxDynamicSharedMemorySize, TG_SMEM);

    __half *p_xrh, *p_agg1h, *p_x1h, *p_agg2h, *p_xsageh, *p_xgath, *p_xrgcnh;
    __half *p_bt1, *p_bt2, *p_btg, *p_btrel, *p_btfus;
    float *p_h, *p_xt, *p_fb2;
    cudaGetSymbolAddress((void**)&p_xrh, g_xrh);
    cudaGetSymbolAddress((void**)&p_agg1h, g_agg1h);
    cudaGetSymbolAddress((void**)&p_x1h, g_x1h);
    cudaGetSymbolAddress((void**)&p_agg2h, g_agg2h);
    cudaGetSymbolAddress((void**)&p_xsageh, g_xsageh);
    cudaGetSymbolAddress((void**)&p_xgath, g_xgath);
    cudaGetSymbolAddress((void**)&p_xrgcnh, g_xrgcnh);
    cudaGetSymbolAddress((void**)&p_bt1, g_bt1);
    cudaGetSymbolAddress((void**)&p_bt2, g_bt2);
    cudaGetSymbolAddress((void**)&p_btg, g_btg);
    cudaGetSymbolAddress((void**)&p_btrel, g_btrel);
    cudaGetSymbolAddress((void**)&p_btfus, g_btfus);
    cudaGetSymbolAddress((void**)&p_h, g_h);
    cudaGetSymbolAddress((void**)&p_xt, g_xt);
    cudaGetSymbolAddress((void**)&p_fb2, g_fb2);

    // ---- setup + CSR build ----
    k_zero_small<<<(NN * RR + 255) / 256, 256>>>();
    k_count<<<(EE + 255) / 256, 256>>>(dst, et);
    k_round_h<<<(NN * IN_C / 4 + 255) / 256, 256>>>((const float4*)x, (__half2*)p_xrh,
                                                    NN * IN_C / 4);
    k_scan1<<<NBLK, 256>>>();
    k_scan2<<<1, 256>>>();
    k_scan3_inv<<<NBLK, 256>>>();
    k_fill<<<(EE + 255) / 256, 256>>>(src, dst, et);

    // all weight transposes (fp32 -> fp16) in ONE launch
    TSegs ts;
    ts.s[0]  = {s1Wl, p_bt1, 128, 256, 256, 0};
    ts.s[1]  = {s1Wr, p_bt1, 128, 256, 256, 128};
    ts.s[2]  = {s2Wl, p_bt2, 256, 256, 512, 0};
    ts.s[3]  = {s2Wr, p_bt2, 256, 256, 512, 256};
    ts.s[4]  = {gatW, p_btg, 256, 512, 256, 0};
    ts.s[5]  = {Wrel + 0 * (size_t)HID * EMBD, p_btrel + 0 * (size_t)128 * 256, 256, 128, 256, 0};
    ts.s[6]  = {Wrel + 1 * (size_t)HID * EMBD, p_btrel + 1 * (size_t)128 * 256, 256, 128, 256, 0};
    ts.s[7]  = {Wrel + 2 * (size_t)HID * EMBD, p_btrel + 2 * (size_t)128 * 256, 256, 128, 256, 0};
    ts.s[8]  = {Wrel + 3 * (size_t)HID * EMBD, p_btrel + 3 * (size_t)128 * 256, 256, 128, 256, 0};
    ts.s[9]  = {fW, p_btfus, 256, 128, 640, 0};
    ts.s[10] = {fW + 512 * EMBD, p_btfus, 128, 128, 640, 512};
    k_transAll<<<dim3(512, 11), 256>>>(ts);
    k_compose<<<HID + 1, EMBD>>>(fW, fB, Wroot, rgcB, p_btfus);

    // ---- SAGE 1 (fused dual-A fp16 GEMM) ----
    k_sage_gather_f<IN_C><<<NN, IN_C>>>(x, p_agg1h);
    launch_seg(p_agg1h, IN_C, p_xrh, IN_C, 0, 0, p_bt1, p_x1h, s1b, NN, HID, 1, 1);

    // ---- SAGE 2 ----
    k_sage_gather_h<HID><<<NN, HID>>>(p_x1h, p_agg2h);
    launch_seg(p_agg2h, HID, p_x1h, HID, 0, 0, p_bt2, p_xsageh, s2b, NN, HID, 1, 1);

    // ---- GAT (fp32 output g_h) ----
    launch_seg(p_xsageh, HID, 0, 0, 0, 0, p_btg, p_h, nullptr, NN, 2 * HID, 0, 0);
    k_al<<<(NN * 2 * 32 + 255) / 256, 256>>>(aSrc, aDst);
    k_gat<<<NN, 256>>>(gatB);

    // ---- RGCN (4 relations via grid.z; fp32 output g_xt) ----
    launch_seg(p_xgath, HID, 0, 0, 0, 0, p_btrel, p_xt, nullptr, NN, EMBD, 0, 0,
               RR, (size_t)128 * 256, (size_t)NN * EMBD);
    k_rgcn<<<NN, 128>>>();

    // ---- Fusion (3-segment, rgcn-root folded; fp32 out) + normalize ----
    launch_seg(p_xsageh, HID, p_xgath, HID, p_xrgcnh, EMBD, p_btfus,
               out, p_fb2, NN, EMBD, 0, 0);
    k_norm<<<NN, 128>>>(out);
}

// round 16
// speedup vs baseline: 1.5430x; 1.0660x over previous
#include <cuda_runtime.h>
#include <cuda_fp16.h>
#include <math.h>

#define NN   50000
#define EE   800000
#define IN_C 128
#define HID  256
#define EMBD 128
#define RR   4
#define NBLK ((NN + 255) / 256)

// ---------------- scratch (device globals; no allocation) ----------------
__device__ int      g_deg[NN];
__device__ float    g_invdeg[NN];
__device__ int      g_cnt4[NN * RR];
__device__ float    g_invcnt4[NN * RR];
__device__ int      g_rowstart[NN];
__device__ int      g_cursor[NN];
__device__ int      g_bsum[256];
__device__ int      g_boff[256];
__device__ int      g_es[EE];
__device__ int      g_etl[EE];
__device__ float    g_als[NN * 2];
__device__ float    g_ald[NN * 2];
__device__ float    g_fb2[EMBD];
// fp16 buffers
__device__ __align__(16) __half g_xrh[(size_t)NN * IN_C];
__device__ __align__(16) __half g_agg1h[(size_t)NN * IN_C];
__device__ __align__(16) __half g_x1h[(size_t)NN * HID];
__device__ __align__(16) __half g_agg2h[(size_t)NN * HID];
__device__ __align__(16) __half g_xsageh[(size_t)NN * HID];
__device__ __align__(16) __half g_hh[(size_t)NN * 2 * HID];       // GAT features (half)
__device__ __align__(16) __half g_xgath[(size_t)NN * HID];
__device__ __align__(16) __half g_xth[(size_t)RR * NN * EMBD];    // RGCN per-rel (half)
__device__ __align__(16) __half g_xrgcnh[(size_t)NN * EMBD];
// fp16 pre-transposed weights Bt[n][k]
__device__ __align__(16) __half g_bt1[256 * 256];
__device__ __align__(16) __half g_bt2[256 * 512];
__device__ __align__(16) __half g_btg[512 * 256];
__device__ __align__(16) __half g_btrel[RR * 128 * 256];
__device__ __align__(16) __half g_btfus[128 * 640];

__device__ __forceinline__ float lrelu(float v) { return v > 0.f ? v : 0.2f * v; }

__device__ __forceinline__ void cp16(unsigned sm, const void* gm) {
    asm volatile("cp.async.cg.shared.global [%0], [%1], 16;" :: "r"(sm), "l"(gm));
}
__device__ __forceinline__ void cpcommit() {
    asm volatile("cp.async.commit_group;");
}
template <int N>
__device__ __forceinline__ void cpwait() {
    asm volatile("cp.async.wait_group %0;" :: "n"(N));
}

// ---------------- zero / counts / scan / fill ----------------
__global__ void k_zero_small() {
    int i = blockIdx.x * blockDim.x + threadIdx.x;
    if (i < NN) { g_deg[i] = 0; g_cursor[i] = 0; }
    if (i < NN * RR) g_cnt4[i] = 0;
}

__global__ void k_count(const int* __restrict__ dst, const int* __restrict__ et) {
    int i = blockIdx.x * blockDim.x + threadIdx.x;
    if (i >= EE) return;
    int d = dst[i];
    atomicAdd(&g_deg[d], 1);
    atomicAdd(&g_cnt4[d * RR + et[i]], 1);
}

__global__ void k_scan1() {
    __shared__ int sh[256];
    int b = blockIdx.x, t = threadIdx.x;
    int i = b * 256 + t;
    int v = (i < NN) ? g_deg[i] : 0;
    sh[t] = v; __syncthreads();
    for (int o = 1; o < 256; o <<= 1) {
        int add = (t >= o) ? sh[t - o] : 0;
        __syncthreads();
        sh[t] += add;
        __syncthreads();
    }
    if (i < NN) g_rowstart[i] = sh[t] - v;
    if (t == 255) g_bsum[b] = sh[255];
}

__global__ void k_scan2() {
    __shared__ int sh[256];
    int t = threadIdx.x;
    int v = (t < NBLK) ? g_bsum[t] : 0;
    sh[t] = v; __syncthreads();
    for (int o = 1; o < 256; o <<= 1) {
        int add = (t >= o) ? sh[t - o] : 0;
        __syncthreads();
        sh[t] += add;
        __syncthreads();
    }
    g_boff[t] = sh[t] - v;
}

__global__ void k_scan3_inv() {
    int i = blockIdx.x * blockDim.x + threadIdx.x;
    if (i >= NN) return;
    g_rowstart[i] += g_boff[i >> 8];
    g_invdeg[i] = 1.f / fmaxf((float)g_deg[i], 1.f);
#pragma unroll
    for (int r = 0; r < RR; r++)
        g_invcnt4[i * RR + r] = 1.f / fmaxf((float)g_cnt4[i * RR + r], 1.f);
}

__global__ void k_fill(const int* __restrict__ src, const int* __restrict__ dst,
                       const int* __restrict__ et) {
    int e = blockIdx.x * blockDim.x + threadIdx.x;
    if (e >= EE) return;
    int d = dst[e];
    int pos = atomicAdd(&g_cursor[d], 1);
    int slot = g_rowstart[d] + pos;
    g_es[slot] = src[e];
    g_etl[slot] = et[e];
}

// ---------------- weight transpose -> fp16 ----------------
struct TSeg { const float* B; __half* Bt; int K; int N; int ldBt; int kOff; };
struct TSegs { TSeg s[11]; };

__global__ void k_transAll(TSegs P) {
    TSeg sg = P.s[blockIdx.y];
    int i = blockIdx.x * blockDim.x + threadIdx.x;
    if (i >= sg.K * sg.N) return;
    int k = i / sg.N, n = i % sg.N;
    sg.Bt[(size_t)n * sg.ldBt + sg.kOff + k] = __float2half_rn(sg.B[(size_t)k * sg.N + n]);
}

__global__ void k_round_h(const float4* __restrict__ in, __half2* __restrict__ out, int n4) {
    int i = blockIdx.x * blockDim.x + threadIdx.x;
    if (i >= n4) return;
    float4 v = in[i];
    out[i * 2 + 0] = __floats2half2_rn(v.x, v.y);
    out[i * 2 + 1] = __floats2half2_rn(v.z, v.w);
}

// ---------------- SAGE mean-gather (float input) ----------------
template <int D>
__global__ __launch_bounds__(D) void k_sage_gather_f(const float* __restrict__ xin,
                                                     __half* __restrict__ agg) {
    constexpr int L = D / 4;
    __shared__ float4 sred[4][L];
    int n = blockIdx.x;
    int tid = threadIdx.x;
    int grp = tid / L, lane = tid % L;
    int base = g_rowstart[n], deg = g_deg[n];
    const float4* xin4 = (const float4*)xin;
    float4 acc = make_float4(0.f, 0.f, 0.f, 0.f);
    for (int j = grp; j < deg; j += 4) {
        int s = g_es[base + j];
        float4 v = xin4[(size_t)s * L + lane];
        acc.x += v.x; acc.y += v.y; acc.z += v.z; acc.w += v.w;
    }
    sred[grp][lane] = acc;
    __syncthreads();
    if (grp == 0) {
        float4 a = sred[0][lane], b = sred[1][lane], c = sred[2][lane], d = sred[3][lane];
        float w = g_invdeg[n];
        __half2* o2 = (__half2*)agg + ((size_t)n * L + lane) * 2;
        o2[0] = __floats2half2_rn((a.x + b.x + c.x + d.x) * w, (a.y + b.y + c.y + d.y) * w);
        o2[1] = __floats2half2_rn((a.z + b.z + c.z + d.z) * w, (a.w + b.w + c.w + d.w) * w);
    }
}

// ---------------- SAGE mean-gather (half input) ----------------
template <int D>
__global__ __launch_bounds__(D) void k_sage_gather_h(const __half* __restrict__ xin,
                                                     __half* __restrict__ agg) {
    constexpr int L = D / 4;
    __shared__ float4 sred[4][L];
    int n = blockIdx.x;
    int tid = threadIdx.x;
    int grp = tid / L, lane = tid % L;
    int base = g_rowstart[n], deg = g_deg[n];
    const __half2* xin2 = (const __half2*)xin;
    float4 acc = make_float4(0.f, 0.f, 0.f, 0.f);
    for (int j = grp; j < deg; j += 4) {
        int s = g_es[base + j];
        size_t p = ((size_t)s * L + lane) * 2;
        float2 f0 = __half22float2(xin2[p]);
        float2 f1 = __half22float2(xin2[p + 1]);
        acc.x += f0.x; acc.y += f0.y; acc.z += f1.x; acc.w += f1.y;
    }
    sred[grp][lane] = acc;
    __syncthreads();
    if (grp == 0) {
        float4 a = sred[0][lane], b = sred[1][lane], c = sred[2][lane], d = sred[3][lane];
        float w = g_invdeg[n];
        __half2* o2 = (__half2*)agg + ((size_t)n * L + lane) * 2;
        o2[0] = __floats2half2_rn((a.x + b.x + c.x + d.x) * w, (a.y + b.y + c.y + d.y) * w);
        o2[1] = __floats2half2_rn((a.z + b.z + c.z + d.z) * w, (a.w + b.w + c.w + d.w) * w);
    }
}

// ---------------- FP16 GEMM: 128x128 tile, K-tile 32, 4-stage cp.async, 1 sync/tile ----------------
__global__ __launch_bounds__(256) void tgemm(
    const __half* __restrict__ A0, int K0,
    const __half* __restrict__ A1, int K1,
    const __half* __restrict__ A2, int K2,
    const __half* __restrict__ Bt,
    void* __restrict__ Cv, const float* __restrict__ bias,
    int M, int Nc, int reluFlag, int halfOut,
    size_t zsB, size_t zsC) {
    extern __shared__ __half smh[];
    __half* smA = smh;                 // 4 stages * 128 rows * 40 halves
    __half* smB = smh + 4 * 5120;
#define ASX(st, r, c) smA[(st) * 5120 + (r) * 40 + (c)]
#define BSX(st, r, c) smB[(st) * 5120 + (r) * 40 + (c)]
    const int tid = threadIdx.x;
    const int m0 = blockIdx.y * 128, n0 = blockIdx.x * 128;
    const int wid = tid >> 5, lane = tid & 31;
    const int wm = wid & 3, wn = wid >> 2;
    const int g = lane >> 2, tq = lane & 3;
    const int Ktot = K0 + K1 + K2;
    Bt += blockIdx.z * zsB;
    const __half* segA[3] = {A0, A1, A2};
    const int segK01 = K0 + K1;
    const int T = Ktot >> 5;

    float acc[2][8][4];
#pragma unroll
    for (int mt = 0; mt < 2; mt++)
#pragma unroll
        for (int nt = 0; nt < 8; nt++)
#pragma unroll
            for (int r = 0; r < 4; r++) acc[mt][nt][r] = 0.f;

    const int aRow = tid >> 1;
    const int aCol = (tid & 1) * 16;
    const bool aValid = (m0 + aRow) < M;
    const int aR = aValid ? (m0 + aRow) : 0;
    const __half* BtRow = Bt + (size_t)(n0 + aRow) * Ktot + aCol;

    const int ldR = lane & 15;
    const int ldC = (lane >> 4) * 8;

    auto issue = [&](int tile, int buf) {
        int kpos = tile * 32;
        int s, kk;
        if (kpos < K0) { s = 0; kk = kpos; }
        else if (kpos < segK01) { s = 1; kk = kpos - K0; }
        else { s = 2; kk = kpos - segK01; }
        int Ks = (s == 0) ? K0 : (s == 1) ? K1 : K2;
        const __half* Ag = segA[s] + (size_t)aR * Ks + kk + aCol;
        unsigned sa = (unsigned)__cvta_generic_to_shared(&ASX(buf, aRow, aCol));
        cp16(sa, Ag); cp16(sa + 16, Ag + 8);
        const __half* Bg = BtRow + kpos;
        unsigned sb = (unsigned)__cvta_generic_to_shared(&BSX(buf, aRow, aCol));
        cp16(sb, Bg); cp16(sb + 16, Bg + 8);
    };

    for (int p = 0; p < 3 && p < T; p++) { issue(p, p); cpcommit(); }

    for (int t = 0; t < T; t++) {
        cpwait<2>();
        __syncthreads();
        if (t + 3 < T) issue(t + 3, (t + 3) & 3);
        cpcommit();
        const int pb = t & 3;
#pragma unroll
        for (int ks = 0; ks < 32; ks += 16) {
            unsigned af[2][4], bf[4][4];
#pragma unroll
            for (int mt = 0; mt < 2; mt++) {
                unsigned addr = (unsigned)__cvta_generic_to_shared(
                    &ASX(pb, wm * 32 + mt * 16 + ldR, ks + ldC));
                asm volatile("ldmatrix.sync.aligned.m8n8.x4.shared.b16 {%0,%1,%2,%3}, [%4];"
                    : "=r"(af[mt][0]), "=r"(af[mt][1]), "=r"(af[mt][2]), "=r"(af[mt][3])
                    : "r"(addr));
            }
#pragma unroll
            for (int np = 0; np < 4; np++) {
                unsigned addr = (unsigned)__cvta_generic_to_shared(
                    &BSX(pb, wn * 64 + np * 16 + ldR, ks + ldC));
                asm volatile("ldmatrix.sync.aligned.m8n8.x4.shared.b16 {%0,%1,%2,%3}, [%4];"
                    : "=r"(bf[np][0]), "=r"(bf[np][1]), "=r"(bf[np][2]), "=r"(bf[np][3])
                    : "r"(addr));
            }
#pragma unroll
            for (int mt = 0; mt < 2; mt++)
#pragma unroll
                for (int nt = 0; nt < 8; nt++) {
                    unsigned b0 = bf[nt >> 1][nt & 1];
                    unsigned b1 = bf[nt >> 1][(nt & 1) + 2];
                    float* c = acc[mt][nt];
                    asm volatile(
                        "mma.sync.aligned.m16n8k16.row.col.f32.f16.f16.f32 "
                        "{%0,%1,%2,%3}, {%4,%5,%6,%7}, {%8,%9}, {%0,%1,%2,%3};"
                        : "+f"(c[0]), "+f"(c[1]), "+f"(c[2]), "+f"(c[3])
                        : "r"(af[mt][0]), "r"(af[mt][1]), "r"(af[mt][2]), "r"(af[mt][3]),
                          "r"(b0), "r"(b1));
                }
        }
    }

    float* Cf = (float*)Cv + blockIdx.z * zsC;
    __half* Ch = (__half*)Cv + blockIdx.z * zsC;
#pragma unroll
    for (int mt = 0; mt < 2; mt++) {
        int r0 = m0 + wm * 32 + mt * 16 + g;
#pragma unroll
        for (int half = 0; half < 2; half++) {
            int row = r0 + half * 8;
            if (row >= M) continue;
#pragma unroll
            for (int nt = 0; nt < 8; nt++) {
                int col = n0 + wn * 64 + nt * 8 + 2 * tq;
                float cx = acc[mt][nt][half * 2 + 0];
                float cy = acc[mt][nt][half * 2 + 1];
                if (bias != nullptr) { cx += bias[col]; cy += bias[col + 1]; }
                if (reluFlag) { cx = fmaxf(cx, 0.f); cy = fmaxf(cy, 0.f); }
                size_t off = (size_t)row * Nc + col;
                if (halfOut) {
                    *(__half2*)(Ch + off) = __floats2half2_rn(cx, cy);
                } else {
                    float2 cv2; cv2.x = cx; cv2.y = cy;
                    *(float2*)(Cf + off) = cv2;
                }
            }
        }
    }
#undef ASX
#undef BSX
}

// ---------------- GAT: per-node attention logits (reads half g_hh) ----------------
__global__ __launch_bounds__(256) void k_al(const float* __restrict__ aS,
                                            const float* __restrict__ aD) {
    int gw = (int)(((size_t)blockIdx.x * blockDim.x + threadIdx.x) >> 5);
    int lane = threadIdx.x & 31;
    if (gw >= NN * 2) return;
    int n = gw >> 1, k = gw & 1;
    const __half2* hp = (const __half2*)(g_hh + (size_t)n * 512 + k * 256);
    const float2* as2 = (const float2*)(aS + k * 256);
    const float2* ad2 = (const float2*)(aD + k * 256);
    float ss = 0.f, sd = 0.f;
#pragma unroll
    for (int it = 0; it < 4; it++) {
        int j = lane + it * 32;          // 128 half2 per head
        float2 h = __half22float2(hp[j]);
        float2 A = as2[j], D = ad2[j];
        ss += h.x * A.x + h.y * A.y;
        sd += h.x * D.x + h.y * D.y;
    }
#pragma unroll
    for (int o = 16; o; o >>= 1) {
        ss += __shfl_down_sync(0xffffffffu, ss, o);
        sd += __shfl_down_sync(0xffffffffu, sd, o);
    }
    if (lane == 0) { g_als[gw] = ss; g_ald[gw] = sd; }
}

// ---------------- GAT: online-softmax; reads half g_hh, writes half g_xgath ----------------
__global__ __launch_bounds__(256) void k_gat(const float* __restrict__ bias) {
    __shared__ float sW0[256], sW1[256];
    __shared__ int   sS[256];
    __shared__ float wm0[8], wm1[8];
    __shared__ float2 stage[128];
    int n = blockIdx.x;
    int t = threadIdx.x;
    int lane = t & 31, warp = t >> 5;
    int base = g_rowstart[n], deg = g_deg[n];

    float ald0 = g_ald[2 * n], ald1 = g_ald[2 * n + 1];
    float m0 = lrelu(g_als[2 * n] + ald0);
    float m1 = lrelu(g_als[2 * n + 1] + ald1);
    float d0 = 1.f, d1 = 1.f;
    const __half2* h2 = (const __half2*)g_hh;   // row = 256 half2
    float2 a = __half22float2(h2[(size_t)n * 256 + t]);
    bool head0 = (t < 128);

    for (int c0 = 0; c0 < deg; c0 += 256) {
        int cnt = min(256, deg - c0);
        float e0 = -1e30f, e1 = -1e30f;
        int sNode = 0;
        if (t < cnt) {
            sNode = g_es[base + c0 + t];
            e0 = lrelu(g_als[2 * sNode] + ald0);
            e1 = lrelu(g_als[2 * sNode + 1] + ald1);
        }
        float w0r = e0, w1r = e1;
#pragma unroll
        for (int o = 16; o; o >>= 1) {
            w0r = fmaxf(w0r, __shfl_xor_sync(0xffffffffu, w0r, o));
            w1r = fmaxf(w1r, __shfl_xor_sync(0xffffffffu, w1r, o));
        }
        if (lane == 0) { wm0[warp] = w0r; wm1[warp] = w1r; }
        __syncthreads();
        float cm0 = wm0[0], cm1 = wm1[0];
#pragma unroll
        for (int w = 1; w < 8; w++) { cm0 = fmaxf(cm0, wm0[w]); cm1 = fmaxf(cm1, wm1[w]); }

        float M0 = fmaxf(m0, cm0), M1 = fmaxf(m1, cm1);
        float sc0 = expf(m0 - M0), sc1 = expf(m1 - M1);
        float scMe = head0 ? sc0 : sc1;
        a.x *= scMe; a.y *= scMe;
        d0 *= sc0; d1 *= sc1; m0 = M0; m1 = M1;

        if (t < cnt) {
            sS[t] = sNode;
            sW0[t] = expf(e0 - m0);
            sW1[t] = expf(e1 - m1);
        }
        __syncthreads();
        for (int j = 0; j < cnt; j++) {
            float w0 = sW0[j], w1 = sW1[j];
            float w = head0 ? w0 : w1;
            float2 hv = __half22float2(h2[(size_t)sS[j] * 256 + t]);
            a.x += w * hv.x; a.y += w * hv.y;
            d0 += w0; d1 += w1;
        }
        __syncthreads();
    }
    float i0 = 1.f / fmaxf(d0, 1e-16f), i1 = 1.f / fmaxf(d1, 1e-16f);
    if (!head0) stage[t - 128] = a;
    __syncthreads();
    if (head0) {
        float2 b1 = stage[t];
        float v0 = 0.5f * (a.x * i0 + b1.x * i1) + bias[2 * t];
        float v1 = 0.5f * (a.y * i0 + b1.y * i1) + bias[2 * t + 1];
        ((__half2*)g_xgath)[(size_t)n * 128 + t] =
            __floats2half2_rn(fmaxf(v0, 0.f), fmaxf(v1, 0.f));
    }
}

// ---------------- RGCN gather (reads half g_xth, writes half) ----------------
__global__ __launch_bounds__(128) void k_rgcn() {
    __shared__ float4 sred[4][32];
    int n = blockIdx.x;
    int t = threadIdx.x;
    int grp = t >> 5, lane = t & 31;
    int base = g_rowstart[n], deg = g_deg[n];
    float w0 = g_invcnt4[n * 4 + 0], w1 = g_invcnt4[n * 4 + 1];
    float w2 = g_invcnt4[n * 4 + 2], w3 = g_invcnt4[n * 4 + 3];
    const __half2* xt2 = (const __half2*)g_xth;   // row = 64 half2
    float4 acc = make_float4(0.f, 0.f, 0.f, 0.f);
    for (int j = grp; j < deg; j += 4) {
        int s = g_es[base + j];
        int r = g_etl[base + j];
        float w = (r == 0) ? w0 : (r == 1) ? w1 : (r == 2) ? w2 : w3;
        size_t p = ((size_t)r * NN + s) * 64 + lane * 2;
        float2 f0 = __half22float2(xt2[p]);
        float2 f1 = __half22float2(xt2[p + 1]);
        acc.x += w * f0.x; acc.y += w * f0.y;
        acc.z += w * f1.x; acc.w += w * f1.y;
    }
    sred[grp][lane] = acc;
    __syncthreads();
    if (grp == 0) {
        float4 A = sred[0][lane], B = sred[1][lane], C = sred[2][lane], D = sred[3][lane];
        __half2* o2 = (__half2*)g_xrgcnh + ((size_t)n * 32 + lane) * 2;
        o2[0] = __floats2half2_rn(A.x + B.x + C.x + D.x, A.y + B.y + C.y + D.y);
        o2[1] = __floats2half2_rn(A.z + B.z + C.z + D.z, A.w + B.w + C.w + D.w);
    }
}

// ---------------- fold rgcn root into fusion weights ----------------
__global__ void k_compose(const float* __restrict__ fW, const float* __restrict__ fB,
                          const float* __restrict__ Wroot, const float* __restrict__ rgcB,
                          __half* __restrict__ btfus) {
    int b = blockIdx.x, t = threadIdx.x;
    const float* F3 = fW + 512 * EMBD;
    if (b < HID) {
        float acc = fW[(256 + b) * EMBD + t];
        for (int h = 0; h < EMBD; h++)
            acc += Wroot[b * EMBD + h] * F3[h * EMBD + t];
        btfus[(size_t)t * 640 + 256 + b] = __float2half_rn(acc);
    } else {
        float acc = fB[t];
        for (int h = 0; h < EMBD; h++)
            acc += rgcB[h] * F3[h * EMBD + t];
        g_fb2[t] = acc;
    }
}

// ---------------- final L2 normalize ----------------
__global__ void k_norm(float* __restrict__ out) {
    int n = blockIdx.x;
    int t = threadIdx.x;
    float v = out[(size_t)n * EMBD + t];
    float s = v * v;
#pragma unroll
    for (int o = 16; o; o >>= 1) s += __shfl_down_sync(0xffffffffu, s, o);
    __shared__ float sh[4];
    if ((t & 31) == 0) sh[t >> 5] = s;
    __syncthreads();
    float tot = sh[0] + sh[1] + sh[2] + sh[3];
    float nrm = fmaxf(sqrtf(tot), 1e-12f);
    out[(size_t)n * EMBD + t] = v / nrm;
}

// ---------------- host ----------------
#define TG_SMEM (4 * 2 * 5120 * 2)

static void launch_seg(const __half* A0, int K0, const __half* A1, int K1,
                       const __half* A2, int K2, const __half* Bt,
                       void* C, const float* bias, int M, int Nc,
                       int relu, int halfOut,
                       int gz = 1, size_t zsB = 0, size_t zsC = 0) {
    dim3 grid(Nc / 128, (M + 127) / 128, gz);
    tgemm<<<grid, 256, TG_SMEM>>>(A0, K0, A1, K1, A2, K2, Bt, C, bias, M, Nc,
                                  relu, halfOut, zsB, zsC);
}

extern "C" void kernel_launch(void* const* d_in, const int* in_sizes, int n_in,
                              void* d_out, int out_size) {
    const float* x    = (const float*)d_in[0];
    const int*   ei   = (const int*)d_in[1];
    const int*   et   = (const int*)d_in[2];
    const float* s1Wl = (const float*)d_in[3];
    const float* s1Wr = (const float*)d_in[4];
    const float* s1b  = (const float*)d_in[5];
    const float* s2Wl = (const float*)d_in[6];
    const float* s2Wr = (const float*)d_in[7];
    const float* s2b  = (const float*)d_in[8];
    const float* gatW = (const float*)d_in[9];
    const float* aSrc = (const float*)d_in[10];
    const float* aDst = (const float*)d_in[11];
    const float* gatB = (const float*)d_in[12];
    const float* Wrel = (const float*)d_in[13];
    const float* Wroot= (const float*)d_in[14];
    const float* rgcB = (const float*)d_in[15];
    const float* fW   = (const float*)d_in[16];
    const float* fB   = (const float*)d_in[17];
    float* out = (float*)d_out;

    const int* src = ei;
    const int* dst = ei + EE;

    cudaFuncSetAttribute(tgemm, cudaFuncAttributeMaxDynamicSharedMemorySize, TG_SMEM);

    __half *p_xrh, *p_agg1h, *p_x1h, *p_agg2h, *p_xsageh, *p_hh, *p_xgath, *p_xth, *p_xrgcnh;
    __half *p_bt1, *p_bt2, *p_btg, *p_btrel, *p_btfus;
    float *p_fb2;
    cudaGetSymbolAddress((void**)&p_xrh, g_xrh);
    cudaGetSymbolAddress((void**)&p_agg1h, g_agg1h);
    cudaGetSymbolAddress((void**)&p_x1h, g_x1h);
    cudaGetSymbolAddress((void**)&p_agg2h, g_agg2h);
    cudaGetSymbolAddress((void**)&p_xsageh, g_xsageh);
    cudaGetSymbolAddress((void**)&p_hh, g_hh);
    cudaGetSymbolAddress((void**)&p_xgath, g_xgath);
    cudaGetSymbolAddress((void**)&p_xth, g_xth);
    cudaGetSymbolAddress((void**)&p_xrgcnh, g_xrgcnh);
    cudaGetSymbolAddress((void**)&p_bt1, g_bt1);
    cudaGetSymbolAddress((void**)&p_bt2, g_bt2);
    cudaGetSymbolAddress((void**)&p_btg, g_btg);
    cudaGetSymbolAddress((void**)&p_btrel, g_btrel);
    cudaGetSymbolAddress((void**)&p_btfus, g_btfus);
    cudaGetSymbolAddress((void**)&p_fb2, g_fb2);

    // ---- setup + CSR build ----
    k_zero_small<<<(NN * RR + 255) / 256, 256>>>();
    k_count<<<(EE + 255) / 256, 256>>>(dst, et);
    k_round_h<<<(NN * IN_C / 4 + 255) / 256, 256>>>((const float4*)x, (__half2*)p_xrh,
                                                    NN * IN_C / 4);
    k_scan1<<<NBLK, 256>>>();
    k_scan2<<<1, 256>>>();
    k_scan3_inv<<<NBLK, 256>>>();
    k_fill<<<(EE + 255) / 256, 256>>>(src, dst, et);

    // all weight transposes (fp32 -> fp16) in ONE launch
    TSegs ts;
    ts.s[0]  = {s1Wl, p_bt1, 128, 256, 256, 0};
    ts.s[1]  = {s1Wr, p_bt1, 128, 256, 256, 128};
    ts.s[2]  = {s2Wl, p_bt2, 256, 256, 512, 0};
    ts.s[3]  = {s2Wr, p_bt2, 256, 256, 512, 256};
    ts.s[4]  = {gatW, p_btg, 256, 512, 256, 0};
    ts.s[5]  = {Wrel + 0 * (size_t)HID * EMBD, p_btrel + 0 * (size_t)128 * 256, 256, 128, 256, 0};
    ts.s[6]  = {Wrel + 1 * (size_t)HID * EMBD, p_btrel + 1 * (size_t)128 * 256, 256, 128, 256, 0};
    ts.s[7]  = {Wrel + 2 * (size_t)HID * EMBD, p_btrel + 2 * (size_t)128 * 256, 256, 128, 256, 0};
    ts.s[8]  = {Wrel + 3 * (size_t)HID * EMBD, p_btrel + 3 * (size_t)128 * 256, 256, 128, 256, 0};
    ts.s[9]  = {fW, p_btfus, 256, 128, 640, 0};
    ts.s[10] = {fW + 512 * EMBD, p_btfus, 128, 128, 640, 512};
    k_transAll<<<dim3(512, 11), 256>>>(ts);
    k_compose<<<HID + 1, EMBD>>>(fW, fB, Wroot, rgcB, p_btfus);

    // ---- SAGE 1 (fused dual-A fp16 GEMM) ----
    k_sage_gather_f<IN_C><<<NN, IN_C>>>(x, p_agg1h);
    launch_seg(p_agg1h, IN_C, p_xrh, IN_C, 0, 0, p_bt1, p_x1h, s1b, NN, HID, 1, 1);

    // ---- SAGE 2 ----
    k_sage_gather_h<HID><<<NN, HID>>>(p_x1h, p_agg2h);
    launch_seg(p_agg2h, HID, p_x1h, HID, 0, 0, p_bt2, p_xsageh, s2b, NN, HID, 1, 1);

    // ---- GAT (half output g_hh) ----
    launch_seg(p_xsageh, HID, 0, 0, 0, 0, p_btg, p_hh, nullptr, NN, 2 * HID, 0, 1);
    k_al<<<(NN * 2 * 32 + 255) / 256, 256>>>(aSrc, aDst);
    k_gat<<<NN, 256>>>(gatB);

    // ---- RGCN (4 relations via grid.z; half output g_xth) ----
    launch_seg(p_xgath, HID, 0, 0, 0, 0, p_btrel, p_xth, nullptr, NN, EMBD, 0, 1,
               RR, (size_t)128 * 256, (size_t)NN * EMBD);
    k_rgcn<<<NN, 128>>>();

    // ---- Fusion (3-segment, rgcn-root folded; fp32 out) + normalize ----
    launch_seg(p_xsageh, HID, p_xgath, HID, p_xrgcnh, EMBD, p_btfus,
               out, p_fb2, NN, EMBD, 0, 0);
    k_norm<<<NN, 128>>>(out);
}

// round 17
// speedup vs baseline: 1.6646x; 1.0788x over previous
#include <cuda_runtime.h>
#include <cuda_fp16.h>
#include <math.h>

#define NN   50000
#define EE   800000
#define IN_C 128
#define HID  256
#define EMBD 128
#define RR   4
#define NBLK ((NN + 255) / 256)

// ---------------- scratch (device globals; no allocation) ----------------
__device__ int      g_deg[NN];
__device__ float    g_invdeg[NN];
__device__ int      g_cnt4[NN * RR];
__device__ float    g_invcnt4[NN * RR];
__device__ int      g_rowstart[NN];
__device__ int      g_cursor[NN];
__device__ int      g_bsum[256];
__device__ int      g_boff[256];
__device__ int      g_es[EE];
__device__ int      g_etl[EE];
__device__ float    g_als[NN * 2];
__device__ float    g_ald[NN * 2];
__device__ float4   g_gmd[NN];          // (m0, m1, invd0, invd1)
__device__ float    g_fb2[EMBD];
// fp16 buffers
__device__ __align__(16) __half g_xrh[(size_t)NN * IN_C];
__device__ __align__(16) __half g_agg1h[(size_t)NN * IN_C];
__device__ __align__(16) __half g_x1h[(size_t)NN * HID];
__device__ __align__(16) __half g_agg2h[(size_t)NN * HID];
__device__ __align__(16) __half g_xsageh[(size_t)NN * HID];
__device__ __align__(16) __half g_hh[(size_t)NN * 2 * HID];
__device__ __align__(16) __half g_xgath[(size_t)NN * HID];
__device__ __align__(16) __half g_xth[(size_t)RR * NN * EMBD];
__device__ __align__(16) __half g_xrgcnh[(size_t)NN * EMBD];
// fp16 pre-transposed weights Bt[n][k]
__device__ __align__(16) __half g_bt1[256 * 256];
__device__ __align__(16) __half g_bt2[256 * 512];
__device__ __align__(16) __half g_btg[512 * 256];
__device__ __align__(16) __half g_btrel[RR * 128 * 256];
__device__ __align__(16) __half g_btfus[128 * 640];

__device__ __forceinline__ float lrelu(float v) { return v > 0.f ? v : 0.2f * v; }

__device__ __forceinline__ void cp16(unsigned sm, const void* gm) {
    asm volatile("cp.async.cg.shared.global [%0], [%1], 16;" :: "r"(sm), "l"(gm));
}
__device__ __forceinline__ void cpcommit() {
    asm volatile("cp.async.commit_group;");
}
template <int N>
__device__ __forceinline__ void cpwait() {
    asm volatile("cp.async.wait_group %0;" :: "n"(N));
}

// ---------------- zero / counts / scan / fill ----------------
__global__ void k_zero_small() {
    int i = blockIdx.x * blockDim.x + threadIdx.x;
    if (i < NN) { g_deg[i] = 0; g_cursor[i] = 0; }
    if (i < NN * RR) g_cnt4[i] = 0;
}

__global__ void k_count(const int* __restrict__ dst, const int* __restrict__ et) {
    int i = blockIdx.x * blockDim.x + threadIdx.x;
    if (i >= EE) return;
    int d = dst[i];
    atomicAdd(&g_deg[d], 1);
    atomicAdd(&g_cnt4[d * RR + et[i]], 1);
}

__global__ void k_scan1() {
    __shared__ int sh[256];
    int b = blockIdx.x, t = threadIdx.x;
    int i = b * 256 + t;
    int v = (i < NN) ? g_deg[i] : 0;
    sh[t] = v; __syncthreads();
    for (int o = 1; o < 256; o <<= 1) {
        int add = (t >= o) ? sh[t - o] : 0;
        __syncthreads();
        sh[t] += add;
        __syncthreads();
    }
    if (i < NN) g_rowstart[i] = sh[t] - v;
    if (t == 255) g_bsum[b] = sh[255];
}

__global__ void k_scan2() {
    __shared__ int sh[256];
    int t = threadIdx.x;
    int v = (t < NBLK) ? g_bsum[t] : 0;
    sh[t] = v; __syncthreads();
    for (int o = 1; o < 256; o <<= 1) {
        int add = (t >= o) ? sh[t - o] : 0;
        __syncthreads();
        sh[t] += add;
        __syncthreads();
    }
    g_boff[t] = sh[t] - v;
}

__global__ void k_scan3_inv() {
    int i = blockIdx.x * blockDim.x + threadIdx.x;
    if (i >= NN) return;
    g_rowstart[i] += g_boff[i >> 8];
    g_invdeg[i] = 1.f / fmaxf((float)g_deg[i], 1.f);
#pragma unroll
    for (int r = 0; r < RR; r++)
        g_invcnt4[i * RR + r] = 1.f / fmaxf((float)g_cnt4[i * RR + r], 1.f);
}

__global__ void k_fill(const int* __restrict__ src, const int* __restrict__ dst,
                       const int* __restrict__ et) {
    int e = blockIdx.x * blockDim.x + threadIdx.x;
    if (e >= EE) return;
    int d = dst[e];
    int pos = atomicAdd(&g_cursor[d], 1);
    int slot = g_rowstart[d] + pos;
    g_es[slot] = src[e];
    g_etl[slot] = et[e];
}

// ---------------- weight transpose -> fp16 ----------------
struct TSeg { const float* B; __half* Bt; int K; int N; int ldBt; int kOff; };
struct TSegs { TSeg s[11]; };

__global__ void k_transAll(TSegs P) {
    TSeg sg = P.s[blockIdx.y];
    int i = blockIdx.x * blockDim.x + threadIdx.x;
    if (i >= sg.K * sg.N) return;
    int k = i / sg.N, n = i % sg.N;
    sg.Bt[(size_t)n * sg.ldBt + sg.kOff + k] = __float2half_rn(sg.B[(size_t)k * sg.N + n]);
}

__global__ void k_round_h(const float4* __restrict__ in, __half2* __restrict__ out, int n4) {
    int i = blockIdx.x * blockDim.x + threadIdx.x;
    if (i >= n4) return;
    float4 v = in[i];
    out[i * 2 + 0] = __floats2half2_rn(v.x, v.y);
    out[i * 2 + 1] = __floats2half2_rn(v.z, v.w);
}

// ---------------- SAGE mean-gather (half input) ----------------
template <int D>
__global__ __launch_bounds__(D) void k_sage_gather_h(const __half* __restrict__ xin,
                                                     __half* __restrict__ agg) {
    constexpr int L = D / 4;
    __shared__ float4 sred[4][L];
    int n = blockIdx.x;
    int tid = threadIdx.x;
    int grp = tid / L, lane = tid % L;
    int base = g_rowstart[n], deg = g_deg[n];
    const __half2* xin2 = (const __half2*)xin;
    float4 acc = make_float4(0.f, 0.f, 0.f, 0.f);
    for (int j = grp; j < deg; j += 4) {
        int s = g_es[base + j];
        size_t p = ((size_t)s * L + lane) * 2;
        float2 f0 = __half22float2(xin2[p]);
        float2 f1 = __half22float2(xin2[p + 1]);
        acc.x += f0.x; acc.y += f0.y; acc.z += f1.x; acc.w += f1.y;
    }
    sred[grp][lane] = acc;
    __syncthreads();
    if (grp == 0) {
        float4 a = sred[0][lane], b = sred[1][lane], c = sred[2][lane], d = sred[3][lane];
        float w = g_invdeg[n];
        __half2* o2 = (__half2*)agg + ((size_t)n * L + lane) * 2;
        o2[0] = __floats2half2_rn((a.x + b.x + c.x + d.x) * w, (a.y + b.y + c.y + d.y) * w);
        o2[1] = __floats2half2_rn((a.z + b.z + c.z + d.z) * w, (a.w + b.w + c.w + d.w) * w);
    }
}

// ---------------- FP16 GEMM: 128x128 tile, K-tile 32, 4-stage cp.async, 1 sync/tile ----------------
__global__ __launch_bounds__(256) void tgemm(
    const __half* __restrict__ A0, int K0,
    const __half* __restrict__ A1, int K1,
    const __half* __restrict__ A2, int K2,
    const __half* __restrict__ Bt,
    void* __restrict__ Cv, const float* __restrict__ bias,
    int M, int Nc, int reluFlag, int halfOut,
    size_t zsB, size_t zsC) {
    extern __shared__ __half smh[];
    __half* smA = smh;
    __half* smB = smh + 4 * 5120;
#define ASX(st, r, c) smA[(st) * 5120 + (r) * 40 + (c)]
#define BSX(st, r, c) smB[(st) * 5120 + (r) * 40 + (c)]
    const int tid = threadIdx.x;
    const int m0 = blockIdx.y * 128, n0 = blockIdx.x * 128;
    const int wid = tid >> 5, lane = tid & 31;
    const int wm = wid & 3, wn = wid >> 2;
    const int g = lane >> 2, tq = lane & 3;
    const int Ktot = K0 + K1 + K2;
    Bt += blockIdx.z * zsB;
    const __half* segA[3] = {A0, A1, A2};
    const int segK01 = K0 + K1;
    const int T = Ktot >> 5;

    float acc[2][8][4];
#pragma unroll
    for (int mt = 0; mt < 2; mt++)
#pragma unroll
        for (int nt = 0; nt < 8; nt++)
#pragma unroll
            for (int r = 0; r < 4; r++) acc[mt][nt][r] = 0.f;

    const int aRow = tid >> 1;
    const int aCol = (tid & 1) * 16;
    const bool aValid = (m0 + aRow) < M;
    const int aR = aValid ? (m0 + aRow) : 0;
    const __half* BtRow = Bt + (size_t)(n0 + aRow) * Ktot + aCol;

    const int ldR = lane & 15;
    const int ldC = (lane >> 4) * 8;

    auto issue = [&](int tile, int buf) {
        int kpos = tile * 32;
        int s, kk;
        if (kpos < K0) { s = 0; kk = kpos; }
        else if (kpos < segK01) { s = 1; kk = kpos - K0; }
        else { s = 2; kk = kpos - segK01; }
        int Ks = (s == 0) ? K0 : (s == 1) ? K1 : K2;
        const __half* Ag = segA[s] + (size_t)aR * Ks + kk + aCol;
        unsigned sa = (unsigned)__cvta_generic_to_shared(&ASX(buf, aRow, aCol));
        cp16(sa, Ag); cp16(sa + 16, Ag + 8);
        const __half* Bg = BtRow + kpos;
        unsigned sb = (unsigned)__cvta_generic_to_shared(&BSX(buf, aRow, aCol));
        cp16(sb, Bg); cp16(sb + 16, Bg + 8);
    };

    for (int p = 0; p < 3 && p < T; p++) { issue(p, p); cpcommit(); }

    for (int t = 0; t < T; t++) {
        cpwait<2>();
        __syncthreads();
        if (t + 3 < T) issue(t + 3, (t + 3) & 3);
        cpcommit();
        const int pb = t & 3;
#pragma unroll
        for (int ks = 0; ks < 32; ks += 16) {
            unsigned af[2][4], bf[4][4];
#pragma unroll
            for (int mt = 0; mt < 2; mt++) {
                unsigned addr = (unsigned)__cvta_generic_to_shared(
                    &ASX(pb, wm * 32 + mt * 16 + ldR, ks + ldC));
                asm volatile("ldmatrix.sync.aligned.m8n8.x4.shared.b16 {%0,%1,%2,%3}, [%4];"
                    : "=r"(af[mt][0]), "=r"(af[mt][1]), "=r"(af[mt][2]), "=r"(af[mt][3])
                    : "r"(addr));
            }
#pragma unroll
            for (int np = 0; np < 4; np++) {
                unsigned addr = (unsigned)__cvta_generic_to_shared(
                    &BSX(pb, wn * 64 + np * 16 + ldR, ks + ldC));
                asm volatile("ldmatrix.sync.aligned.m8n8.x4.shared.b16 {%0,%1,%2,%3}, [%4];"
                    : "=r"(bf[np][0]), "=r"(bf[np][1]), "=r"(bf[np][2]), "=r"(bf[np][3])
                    : "r"(addr));
            }
#pragma unroll
            for (int mt = 0; mt < 2; mt++)
#pragma unroll
                for (int nt = 0; nt < 8; nt++) {
                    unsigned b0 = bf[nt >> 1][nt & 1];
                    unsigned b1 = bf[nt >> 1][(nt & 1) + 2];
                    float* c = acc[mt][nt];
                    asm volatile(
                        "mma.sync.aligned.m16n8k16.row.col.f32.f16.f16.f32 "
                        "{%0,%1,%2,%3}, {%4,%5,%6,%7}, {%8,%9}, {%0,%1,%2,%3};"
                        : "+f"(c[0]), "+f"(c[1]), "+f"(c[2]), "+f"(c[3])
                        : "r"(af[mt][0]), "r"(af[mt][1]), "r"(af[mt][2]), "r"(af[mt][3]),
                          "r"(b0), "r"(b1));
                }
        }
    }

    float* Cf = (float*)Cv + blockIdx.z * zsC;
    __half* Ch = (__half*)Cv + blockIdx.z * zsC;
#pragma unroll
    for (int mt = 0; mt < 2; mt++) {
        int r0 = m0 + wm * 32 + mt * 16 + g;
#pragma unroll
        for (int half = 0; half < 2; half++) {
            int row = r0 + half * 8;
            if (row >= M) continue;
#pragma unroll
            for (int nt = 0; nt < 8; nt++) {
                int col = n0 + wn * 64 + nt * 8 + 2 * tq;
                float cx = acc[mt][nt][half * 2 + 0];
                float cy = acc[mt][nt][half * 2 + 1];
                if (bias != nullptr) { cx += bias[col]; cy += bias[col + 1]; }
                if (reluFlag) { cx = fmaxf(cx, 0.f); cy = fmaxf(cy, 0.f); }
                size_t off = (size_t)row * Nc + col;
                if (halfOut) {
                    *(__half2*)(Ch + off) = __floats2half2_rn(cx, cy);
                } else {
                    float2 cv2; cv2.x = cx; cv2.y = cy;
                    *(float2*)(Cf + off) = cv2;
                }
            }
        }
    }
#undef ASX
#undef BSX
}

// ---------------- GAT: per-node attention logits (reads half g_hh) ----------------
__global__ __launch_bounds__(256) void k_al(const float* __restrict__ aS,
                                            const float* __restrict__ aD) {
    int gw = (int)(((size_t)blockIdx.x * blockDim.x + threadIdx.x) >> 5);
    int lane = threadIdx.x & 31;
    if (gw >= NN * 2) return;
    int n = gw >> 1, k = gw & 1;
    const __half2* hp = (const __half2*)(g_hh + (size_t)n * 512 + k * 256);
    const float2* as2 = (const float2*)(aS + k * 256);
    const float2* ad2 = (const float2*)(aD + k * 256);
    float ss = 0.f, sd = 0.f;
#pragma unroll
    for (int it = 0; it < 4; it++) {
        int j = lane + it * 32;
        float2 h = __half22float2(hp[j]);
        float2 A = as2[j], D = ad2[j];
        ss += h.x * A.x + h.y * A.y;
        sd += h.x * D.x + h.y * D.y;
    }
#pragma unroll
    for (int o = 16; o; o >>= 1) {
        ss += __shfl_down_sync(0xffffffffu, ss, o);
        sd += __shfl_down_sync(0xffffffffu, sd, o);
    }
    if (lane == 0) { g_als[gw] = ss; g_ald[gw] = sd; }
}

// ---------------- GAT: per-node max/denominator (one warp per node) ----------------
__global__ __launch_bounds__(256) void k_gatmd() {
    int gw = blockIdx.x * 8 + (threadIdx.x >> 5);
    int lane = threadIdx.x & 31;
    if (gw >= NN) return;
    int n = gw;
    int base = g_rowstart[n], deg = g_deg[n];
    float ald0 = g_ald[2 * n], ald1 = g_ald[2 * n + 1];
    float selfE0 = lrelu(g_als[2 * n] + ald0);
    float selfE1 = lrelu(g_als[2 * n + 1] + ald1);
    float m0 = selfE0, m1 = selfE1;
    for (int j = lane; j < deg; j += 32) {
        int s = g_es[base + j];
        m0 = fmaxf(m0, lrelu(g_als[2 * s] + ald0));
        m1 = fmaxf(m1, lrelu(g_als[2 * s + 1] + ald1));
    }
#pragma unroll
    for (int o = 16; o; o >>= 1) {
        m0 = fmaxf(m0, __shfl_xor_sync(0xffffffffu, m0, o));
        m1 = fmaxf(m1, __shfl_xor_sync(0xffffffffu, m1, o));
    }
    float d0 = (lane == 0) ? expf(selfE0 - m0) : 0.f;
    float d1 = (lane == 0) ? expf(selfE1 - m1) : 0.f;
    for (int j = lane; j < deg; j += 32) {
        int s = g_es[base + j];
        d0 += expf(lrelu(g_als[2 * s] + ald0) - m0);
        d1 += expf(lrelu(g_als[2 * s + 1] + ald1) - m1);
    }
#pragma unroll
    for (int o = 16; o; o >>= 1) {
        d0 += __shfl_xor_sync(0xffffffffu, d0, o);
        d1 += __shfl_xor_sync(0xffffffffu, d1, o);
    }
    if (lane == 0)
        g_gmd[n] = make_float4(m0, m1, 1.f / fmaxf(d0, 1e-16f), 1.f / fmaxf(d1, 1e-16f));
}

// ---------------- GAT: weighted gather with precomputed softmax stats ----------------
__global__ __launch_bounds__(256) void k_gat(const float* __restrict__ bias) {
    __shared__ float sW0[256], sW1[256];
    __shared__ int   sS[256];
    __shared__ float2 stage[128];
    int n = blockIdx.x;
    int t = threadIdx.x;
    int base = g_rowstart[n], deg = g_deg[n];

    float4 md = g_gmd[n];
    float ald0 = g_ald[2 * n], ald1 = g_ald[2 * n + 1];
    float selfE0 = lrelu(g_als[2 * n] + ald0);
    float selfE1 = lrelu(g_als[2 * n + 1] + ald1);
    const __half2* h2 = (const __half2*)g_hh;
    float2 a = __half22float2(h2[(size_t)n * 256 + t]);
    bool head0 = (t < 128);
    float wSelf = head0 ? expf(selfE0 - md.x) * md.z : expf(selfE1 - md.y) * md.w;
    a.x *= wSelf; a.y *= wSelf;

    for (int c0 = 0; c0 < deg; c0 += 256) {
        int cnt = min(256, deg - c0);
        if (t < cnt) {
            int s = g_es[base + c0 + t];
            sS[t] = s;
            sW0[t] = expf(lrelu(g_als[2 * s] + ald0) - md.x) * md.z;
            sW1[t] = expf(lrelu(g_als[2 * s + 1] + ald1) - md.y) * md.w;
        }
        __syncthreads();
        for (int j = 0; j < cnt; j++) {
            float w = head0 ? sW0[j] : sW1[j];
            float2 hv = __half22float2(h2[(size_t)sS[j] * 256 + t]);
            a.x += w * hv.x; a.y += w * hv.y;
        }
        __syncthreads();
    }
    if (!head0) stage[t - 128] = a;
    __syncthreads();
    if (head0) {
        float2 b1 = stage[t];
        float v0 = 0.5f * (a.x + b1.x) + bias[2 * t];
        float v1 = 0.5f * (a.y + b1.y) + bias[2 * t + 1];
        ((__half2*)g_xgath)[(size_t)n * 128 + t] =
            __floats2half2_rn(fmaxf(v0, 0.f), fmaxf(v1, 0.f));
    }
}

// ---------------- RGCN gather (half in/out) ----------------
__global__ __launch_bounds__(128) void k_rgcn() {
    __shared__ float4 sred[4][32];
    int n = blockIdx.x;
    int t = threadIdx.x;
    int grp = t >> 5, lane = t & 31;
    int base = g_rowstart[n], deg = g_deg[n];
    float w0 = g_invcnt4[n * 4 + 0], w1 = g_invcnt4[n * 4 + 1];
    float w2 = g_invcnt4[n * 4 + 2], w3 = g_invcnt4[n * 4 + 3];
    const __half2* xt2 = (const __half2*)g_xth;
    float4 acc = make_float4(0.f, 0.f, 0.f, 0.f);
    for (int j = grp; j < deg; j += 4) {
        int s = g_es[base + j];
        int r = g_etl[base + j];
        float w = (r == 0) ? w0 : (r == 1) ? w1 : (r == 2) ? w2 : w3;
        size_t p = ((size_t)r * NN + s) * 64 + lane * 2;
        float2 f0 = __half22float2(xt2[p]);
        float2 f1 = __half22float2(xt2[p + 1]);
        acc.x += w * f0.x; acc.y += w * f0.y;
        acc.z += w * f1.x; acc.w += w * f1.y;
    }
    sred[grp][lane] = acc;
    __syncthreads();
    if (grp == 0) {
        float4 A = sred[0][lane], B = sred[1][lane], C = sred[2][lane], D = sred[3][lane];
        __half2* o2 = (__half2*)g_xrgcnh + ((size_t)n * 32 + lane) * 2;
        o2[0] = __floats2half2_rn(A.x + B.x + C.x + D.x, A.y + B.y + C.y + D.y);
        o2[1] = __floats2half2_rn(A.z + B.z + C.z + D.z, A.w + B.w + C.w + D.w);
    }
}

// ---------------- fold rgcn root into fusion weights ----------------
__global__ void k_compose(const float* __restrict__ fW, const float* __restrict__ fB,
                          const float* __restrict__ Wroot, const float* __restrict__ rgcB,
                          __half* __restrict__ btfus) {
    int b = blockIdx.x, t = threadIdx.x;
    const float* F3 = fW + 512 * EMBD;
    if (b < HID) {
        float acc = fW[(256 + b) * EMBD + t];
        for (int h = 0; h < EMBD; h++)
            acc += Wroot[b * EMBD + h] * F3[h * EMBD + t];
        btfus[(size_t)t * 640 + 256 + b] = __float2half_rn(acc);
    } else {
        float acc = fB[t];
        for (int h = 0; h < EMBD; h++)
            acc += rgcB[h] * F3[h * EMBD + t];
        g_fb2[t] = acc;
    }
}

// ---------------- final L2 normalize ----------------
__global__ void k_norm(float* __restrict__ out) {
    int n = blockIdx.x;
    int t = threadIdx.x;
    float v = out[(size_t)n * EMBD + t];
    float s = v * v;
#pragma unroll
    for (int o = 16; o; o >>= 1) s += __shfl_down_sync(0xffffffffu, s, o);
    __shared__ float sh[4];
    if ((t & 31) == 0) sh[t >> 5] = s;
    __syncthreads();
    float tot = sh[0] + sh[1] + sh[2] + sh[3];
    float nrm = fmaxf(sqrtf(tot), 1e-12f);
    out[(size_t)n * EMBD + t] = v / nrm;
}

// ---------------- host ----------------
#define TG_SMEM (4 * 2 * 5120 * 2)

static void launch_seg(const __half* A0, int K0, const __half* A1, int K1,
                       const __half* A2, int K2, const __half* Bt,
                       void* C, const float* bias, int M, int Nc,
                       int relu, int halfOut,
                       int gz = 1, size_t zsB = 0, size_t zsC = 0) {
    dim3 grid(Nc / 128, (M + 127) / 128, gz);
    tgemm<<<grid, 256, TG_SMEM>>>(A0, K0, A1, K1, A2, K2, Bt, C, bias, M, Nc,
                                  relu, halfOut, zsB, zsC);
}

extern "C" void kernel_launch(void* const* d_in, const int* in_sizes, int n_in,
                              void* d_out, int out_size) {
    const float* x    = (const float*)d_in[0];
    const int*   ei   = (const int*)d_in[1];
    const int*   et   = (const int*)d_in[2];
    const float* s1Wl = (const float*)d_in[3];
    const float* s1Wr = (const float*)d_in[4];
    const float* s1b  = (const float*)d_in[5];
    const float* s2Wl = (const float*)d_in[6];
    const float* s2Wr = (const float*)d_in[7];
    const float* s2b  = (const float*)d_in[8];
    const float* gatW = (const float*)d_in[9];
    const float* aSrc = (const float*)d_in[10];
    const float* aDst = (const float*)d_in[11];
    const float* gatB = (const float*)d_in[12];
    const float* Wrel = (const float*)d_in[13];
    const float* Wroot= (const float*)d_in[14];
    const float* rgcB = (const float*)d_in[15];
    const float* fW   = (const float*)d_in[16];
    const float* fB   = (const float*)d_in[17];
    float* out = (float*)d_out;

    const int* src = ei;
    const int* dst = ei + EE;

    cudaFuncSetAttribute(tgemm, cudaFuncAttributeMaxDynamicSharedMemorySize, TG_SMEM);

    __half *p_xrh, *p_agg1h, *p_x1h, *p_agg2h, *p_xsageh, *p_hh, *p_xgath, *p_xth, *p_xrgcnh;
    __half *p_bt1, *p_bt2, *p_btg, *p_btrel, *p_btfus;
    float *p_fb2;
    cudaGetSymbolAddress((void**)&p_xrh, g_xrh);
    cudaGetSymbolAddress((void**)&p_agg1h, g_agg1h);
    cudaGetSymbolAddress((void**)&p_x1h, g_x1h);
    cudaGetSymbolAddress((void**)&p_agg2h, g_agg2h);
    cudaGetSymbolAddress((void**)&p_xsageh, g_xsageh);
    cudaGetSymbolAddress((void**)&p_hh, g_hh);
    cudaGetSymbolAddress((void**)&p_xgath, g_xgath);
    cudaGetSymbolAddress((void**)&p_xth, g_xth);
    cudaGetSymbolAddress((void**)&p_xrgcnh, g_xrgcnh);
    cudaGetSymbolAddress((void**)&p_bt1, g_bt1);
    cudaGetSymbolAddress((void**)&p_bt2, g_bt2);
    cudaGetSymbolAddress((void**)&p_btg, g_btg);
    cudaGetSymbolAddress((void**)&p_btrel, g_btrel);
    cudaGetSymbolAddress((void**)&p_btfus, g_btfus);
    cudaGetSymbolAddress((void**)&p_fb2, g_fb2);

    // ---- setup + CSR build ----
    k_zero_small<<<(NN * RR + 255) / 256, 256>>>();
    k_count<<<(EE + 255) / 256, 256>>>(dst, et);
    k_round_h<<<(NN * IN_C / 4 + 255) / 256, 256>>>((const float4*)x, (__half2*)p_xrh,
                                                    NN * IN_C / 4);
    k_scan1<<<NBLK, 256>>>();
    k_scan2<<<1, 256>>>();
    k_scan3_inv<<<NBLK, 256>>>();
    k_fill<<<(EE + 255) / 256, 256>>>(src, dst, et);

    // all weight transposes (fp32 -> fp16) in ONE launch
    TSegs ts;
    ts.s[0]  = {s1Wl, p_bt1, 128, 256, 256, 0};
    ts.s[1]  = {s1Wr, p_bt1, 128, 256, 256, 128};
    ts.s[2]  = {s2Wl, p_bt2, 256, 256, 512, 0};
    ts.s[3]  = {s2Wr, p_bt2, 256, 256, 512, 256};
    ts.s[4]  = {gatW, p_btg, 256, 512, 256, 0};
    ts.s[5]  = {Wrel + 0 * (size_t)HID * EMBD, p_btrel + 0 * (size_t)128 * 256, 256, 128, 256, 0};
    ts.s[6]  = {Wrel + 1 * (size_t)HID * EMBD, p_btrel + 1 * (size_t)128 * 256, 256, 128, 256, 0};
    ts.s[7]  = {Wrel + 2 * (size_t)HID * EMBD, p_btrel + 2 * (size_t)128 * 256, 256, 128, 256, 0};
    ts.s[8]  = {Wrel + 3 * (size_t)HID * EMBD, p_btrel + 3 * (size_t)128 * 256, 256, 128, 256, 0};
    ts.s[9]  = {fW, p_btfus, 256, 128, 640, 0};
    ts.s[10] = {fW + 512 * EMBD, p_btfus, 128, 128, 640, 512};
    k_transAll<<<dim3(512, 11), 256>>>(ts);
    k_compose<<<HID + 1, EMBD>>>(fW, fB, Wroot, rgcB, p_btfus);

    // ---- SAGE 1 (gather reads fp16 x; fused dual-A GEMM) ----
    k_sage_gather_h<IN_C><<<NN, IN_C>>>(p_xrh, p_agg1h);
    launch_seg(p_agg1h, IN_C, p_xrh, IN_C, 0, 0, p_bt1, p_x1h, s1b, NN, HID, 1, 1);

    // ---- SAGE 2 ----
    k_sage_gather_h<HID><<<NN, HID>>>(p_x1h, p_agg2h);
    launch_seg(p_agg2h, HID, p_x1h, HID, 0, 0, p_bt2, p_xsageh, s2b, NN, HID, 1, 1);

    // ---- GAT ----
    launch_seg(p_xsageh, HID, 0, 0, 0, 0, p_btg, p_hh, nullptr, NN, 2 * HID, 0, 1);
    k_al<<<(NN * 2 * 32 + 255) / 256, 256>>>(aSrc, aDst);
    k_gatmd<<<(NN + 7) / 8, 256>>>();
    k_gat<<<NN, 256>>>(gatB);

    // ---- RGCN (4 relations via grid.z) ----
    launch_seg(p_xgath, HID, 0, 0, 0, 0, p_btrel, p_xth, nullptr, NN, EMBD, 0, 1,
               RR, (size_t)128 * 256, (size_t)NN * EMBD);
    k_rgcn<<<NN, 128>>>();

    // ---- Fusion (3-segment, rgcn-root folded; fp32 out) + normalize ----
    launch_seg(p_xsageh, HID, p_xgath, HID, p_xrgcnh, EMBD, p_btfus,
               out, p_fb2, NN, EMBD, 0, 0);
    k_norm<<<NN, 128>>>(out);
}